// round 8
// baseline (speedup 1.0000x reference)
#include <cuda_runtime.h>
#include <cstdint>

// ---------------------------------------------------------------------------
// MHA on mma.sync m16n8k8 tf32.  R8: attention barrier decorrelation —
// split CTA to 128 threads / 4 warps (mt=2, 32 q rows per warp unchanged),
// 2 CTAs/SM so staging barriers of one CTA overlap compute of the other.
// GEMMs unchanged.
// ---------------------------------------------------------------------------

#define SEQ     2048
#define BATCH   2
#define NH      16
#define HD      64
#define HID     1024
#define MROWS   (BATCH * SEQ)   // 4096

__device__ float g_Q[MROWS * HID];
__device__ float g_K[MROWS * HID];
__device__ float g_V[MROWS * HID];
__device__ float g_O[MROWS * HID];

// ------------------------------ helpers ------------------------------------
__device__ __forceinline__ float tf32r(float f) {
    uint32_t r;
    asm("cvt.rna.tf32.f32 %0, %1;" : "=r"(r) : "f"(f));
    return __uint_as_float(r);
}

__device__ __forceinline__ void mma_tf32(float* d, const uint32_t* a,
                                         uint32_t b0, uint32_t b1) {
    asm volatile(
        "mma.sync.aligned.m16n8k8.row.col.f32.tf32.tf32.f32 "
        "{%0,%1,%2,%3}, {%4,%5,%6,%7}, {%8,%9}, {%0,%1,%2,%3};"
        : "+f"(d[0]), "+f"(d[1]), "+f"(d[2]), "+f"(d[3])
        : "r"(a[0]), "r"(a[1]), "r"(a[2]), "r"(a[3]), "r"(b0), "r"(b1));
}

// ============================ tf32 GEMM (unchanged, passing) ================
#define PADA 36
#define PADB 136
#define GEMM_SMEM ((2 * (128 * PADA + 32 * PADB)) * (int)sizeof(float))

__global__ __launch_bounds__(256) void gemm_tc(
    const float* __restrict__ A, int lda,
    const float* __restrict__ B, int ldb,
    const float* __restrict__ bias,
    float* __restrict__ C, int ldc, int K)
{
    extern __shared__ float smg[];
    float* As = smg;
    float* Bs = smg + 2 * 128 * PADA;

    const int tid  = threadIdx.x;
    const int wid  = tid >> 5, lane = tid & 31;
    const int g    = lane >> 2, t = lane & 3;
    const int wr   = wid & 1,  wc = wid >> 1;
    const int row0 = blockIdx.y * 128;
    const int col0 = blockIdx.x * 128;

    const int ar = tid >> 3, ac = (tid & 7) * 4;
    const int br = tid >> 3, bc = (tid & 7) * 4;

    const float* Ag = A + (size_t)row0 * lda;
    const float* Bg = B + col0;

    float4 ra[4], rb[4];
    const int NT = K >> 5;

    #pragma unroll
    for (int i = 0; i < 4; i++)
        ra[i] = *(const float4*)(Ag + (size_t)(ar + 32 * i) * lda + ac);
    #pragma unroll
    for (int j = 0; j < 4; j++)
        rb[j] = *(const float4*)(Bg + (size_t)br * ldb + bc + 32 * j);
    {
        #pragma unroll
        for (int i = 0; i < 4; i++) {
            float* d = As + (ar + 32 * i) * PADA + ac;
            d[0] = tf32r(ra[i].x); d[1] = tf32r(ra[i].y);
            d[2] = tf32r(ra[i].z); d[3] = tf32r(ra[i].w);
        }
        #pragma unroll
        for (int j = 0; j < 4; j++) {
            float* d = Bs + br * PADB + bc + 32 * j;
            d[0] = tf32r(rb[j].x); d[1] = tf32r(rb[j].y);
            d[2] = tf32r(rb[j].z); d[3] = tf32r(rb[j].w);
        }
    }
    __syncthreads();

    float acc[4][4][4] = {};

    for (int kt = 0; kt < NT; kt++) {
        if (kt + 1 < NT) {
            const int k0 = (kt + 1) * 32;
            #pragma unroll
            for (int i = 0; i < 4; i++)
                ra[i] = *(const float4*)(Ag + (size_t)(ar + 32 * i) * lda + k0 + ac);
            #pragma unroll
            for (int j = 0; j < 4; j++)
                rb[j] = *(const float4*)(Bg + (size_t)(k0 + br) * ldb + bc + 32 * j);
        }

        const float* Ac = As + (kt & 1) * 128 * PADA;
        const float* Bc = Bs + (kt & 1) * 32 * PADB;

        #pragma unroll
        for (int kk = 0; kk < 4; kk++) {
            uint32_t af[4][4];
            #pragma unroll
            for (int mt = 0; mt < 4; mt++) {
                const float* ap = Ac + (wr * 64 + mt * 16) * PADA + kk * 8;
                af[mt][0] = __float_as_uint(ap[ g      * PADA + t    ]);
                af[mt][1] = __float_as_uint(ap[(g + 8) * PADA + t    ]);
                af[mt][2] = __float_as_uint(ap[ g      * PADA + t + 4]);
                af[mt][3] = __float_as_uint(ap[(g + 8) * PADA + t + 4]);
            }
            #pragma unroll
            for (int nt = 0; nt < 4; nt++) {
                const float* bp = Bc + kk * 8 * PADB + wc * 32 + nt * 8 + g;
                uint32_t b0 = __float_as_uint(bp[ t      * PADB]);
                uint32_t b1 = __float_as_uint(bp[(t + 4) * PADB]);
                #pragma unroll
                for (int mt = 0; mt < 4; mt++)
                    mma_tf32(acc[mt][nt], af[mt], b0, b1);
            }
        }

        if (kt + 1 < NT) {
            __syncthreads();
            float* Ad = As + ((kt + 1) & 1) * 128 * PADA;
            float* Bd = Bs + ((kt + 1) & 1) * 32 * PADB;
            #pragma unroll
            for (int i = 0; i < 4; i++) {
                float* d = Ad + (ar + 32 * i) * PADA + ac;
                d[0] = tf32r(ra[i].x); d[1] = tf32r(ra[i].y);
                d[2] = tf32r(ra[i].z); d[3] = tf32r(ra[i].w);
            }
            #pragma unroll
            for (int j = 0; j < 4; j++) {
                float* d = Bd + br * PADB + bc + 32 * j;
                d[0] = tf32r(rb[j].x); d[1] = tf32r(rb[j].y);
                d[2] = tf32r(rb[j].z); d[3] = tf32r(rb[j].w);
            }
            __syncthreads();
        }
    }

    #pragma unroll
    for (int mt = 0; mt < 4; mt++) {
        const int row = row0 + wr * 64 + mt * 16 + g;
        #pragma unroll
        for (int nt = 0; nt < 4; nt++) {
            const int col = col0 + wc * 32 + nt * 8 + 2 * t;
            float2 bb = *(const float2*)&bias[col];
            float2 v0 = {acc[mt][nt][0] + bb.x, acc[mt][nt][1] + bb.y};
            float2 v1 = {acc[mt][nt][2] + bb.x, acc[mt][nt][3] + bb.y};
            *(float2*)&C[(size_t)row * ldc + col]       = v0;
            *(float2*)&C[(size_t)(row + 8) * ldc + col] = v1;
        }
    }
}

// ============================ attention ====================================
// 128 q rows/CTA, 4 warps x 32 q rows (mt=2), 2 CTAs/SM.
#define ATP 68
#define ATTN_SMEM ((2 * 64 * ATP + 128 * ATP) * (int)sizeof(float))   // 69632

__global__ __launch_bounds__(128, 2) void attn_tc(
    const float* __restrict__ Q,
    const float* __restrict__ Kin,
    const float* __restrict__ V,
    float* __restrict__ O)
{
    extern __shared__ float sma[];
    float* Ks = sma;                   // [j][d] 64xATP
    float* Vt = sma + 64 * ATP;        // [d][j] 64xATP
    float* Ps = sma + 2 * 64 * ATP;    // Q stage (128xATP), then P slabs (4w x 32r)

    const int tid  = threadIdx.x;
    const int wid  = tid >> 5, lane = tid & 31;
    const int g    = lane >> 2, t = lane & 3;
    const int b    = blockIdx.z;
    const int h    = blockIdx.y;
    const int q0   = blockIdx.x * 128;
    const float C2 = 0.125f * 1.44269504088896340736f;   // scale*log2(e)

    const float* Qg = Q   + ((size_t)b * SEQ + q0) * HID + h * HD;
    const float* Kg = Kin + (size_t)b * SEQ * HID + h * HD;
    const float* Vg = V   + (size_t)b * SEQ * HID + h * HD;

    // ---- stage Q (tf32) into Ps, preload fragments, then Ps is P slabs ----
    for (int idx = tid; idx < 128 * 16; idx += 128) {
        const int r = idx >> 4, d4 = (idx & 15) * 4;
        float4 v = *(const float4*)(Qg + (size_t)r * HID + d4);
        float* d = Ps + r * ATP + d4;
        d[0] = tf32r(v.x); d[1] = tf32r(v.y); d[2] = tf32r(v.z); d[3] = tf32r(v.w);
    }
    __syncthreads();

    uint32_t qf[2][8][4];
    #pragma unroll
    for (int mt = 0; mt < 2; mt++) {
        #pragma unroll
        for (int ks = 0; ks < 8; ks++) {
            const float* qp = Ps + (wid * 32 + mt * 16) * ATP + ks * 8;
            qf[mt][ks][0] = __float_as_uint(qp[ g      * ATP + t    ]);
            qf[mt][ks][1] = __float_as_uint(qp[(g + 8) * ATP + t    ]);
            qf[mt][ks][2] = __float_as_uint(qp[ g      * ATP + t + 4]);
            qf[mt][ks][3] = __float_as_uint(qp[(g + 8) * ATP + t + 4]);
        }
    }
    __syncthreads();

    float oacc[2][8][4] = {};
    float m[2][2], l[2][2];
    #pragma unroll
    for (int mt = 0; mt < 2; mt++) {
        m[mt][0] = -1e30f; m[mt][1] = -1e30f;
        l[mt][0] = 0.0f;   l[mt][1] = 0.0f;
    }

    // staging maps (128 threads, 64x64 tiles: 32 floats = 8 float4 each)
    const int jk = tid >> 1, dk = (tid & 1) * 32;    // K: [j][d]
    const int jv = tid & 63, dv = (tid >> 6) * 32;   // V: write [d][j]

    float* Pw = Ps + wid * 32 * ATP;

    for (int kv0 = 0; kv0 < SEQ; kv0 += 64) {
        __syncthreads();   // prior tile's consumers done
        #pragma unroll
        for (int i = 0; i < 8; i++) {
            float4 kv4 = *(const float4*)(Kg + (size_t)(kv0 + jk) * HID + dk + 4 * i);
            float* kd = Ks + jk * ATP + dk + 4 * i;
            kd[0] = tf32r(kv4.x); kd[1] = tf32r(kv4.y);
            kd[2] = tf32r(kv4.z); kd[3] = tf32r(kv4.w);
        }
        #pragma unroll
        for (int i = 0; i < 8; i++) {
            float4 vv = *(const float4*)(Vg + (size_t)(kv0 + jv) * HID + dv + 4 * i);
            const int d = dv + 4 * i;
            Vt[(d + 0) * ATP + jv] = tf32r(vv.x);
            Vt[(d + 1) * ATP + jv] = tf32r(vv.y);
            Vt[(d + 2) * ATP + jv] = tf32r(vv.z);
            Vt[(d + 3) * ATP + jv] = tf32r(vv.w);
        }
        __syncthreads();

        // ---- S = Q K^T : one B load feeds both mt ----
        float s[2][8][4] = {};
        #pragma unroll
        for (int nt = 0; nt < 8; nt++) {
            #pragma unroll
            for (int ks = 0; ks < 8; ks++) {
                const float* bp = Ks + (nt * 8 + g) * ATP + ks * 8 + t;
                uint32_t b0 = __float_as_uint(bp[0]);
                uint32_t b1 = __float_as_uint(bp[4]);
                mma_tf32(s[0][nt], qf[0][ks], b0, b1);
                mma_tf32(s[1][nt], qf[1][ks], b0, b1);
            }
        }

        // ---- online softmax per mt (raw-score max, exp2-folded) ----
        #pragma unroll
        for (int mt = 0; mt < 2; mt++) {
            float rm0 = -1e30f, rm1 = -1e30f;
            #pragma unroll
            for (int nt = 0; nt < 8; nt++) {
                rm0 = fmaxf(rm0, fmaxf(s[mt][nt][0], s[mt][nt][1]));
                rm1 = fmaxf(rm1, fmaxf(s[mt][nt][2], s[mt][nt][3]));
            }
            rm0 = fmaxf(rm0, __shfl_xor_sync(0xffffffffu, rm0, 1));
            rm0 = fmaxf(rm0, __shfl_xor_sync(0xffffffffu, rm0, 2));
            rm1 = fmaxf(rm1, __shfl_xor_sync(0xffffffffu, rm1, 1));
            rm1 = fmaxf(rm1, __shfl_xor_sync(0xffffffffu, rm1, 2));

            const float nm0 = fmaxf(m[mt][0], rm0), nm1 = fmaxf(m[mt][1], rm1);
            const float a0 = exp2f((m[mt][0] - nm0) * C2);
            const float a1 = exp2f((m[mt][1] - nm1) * C2);
            const float mc0 = nm0 * C2, mc1 = nm1 * C2;
            float sum0 = 0.0f, sum1 = 0.0f;
            #pragma unroll
            for (int nt = 0; nt < 8; nt++) {
                s[mt][nt][0] = exp2f(fmaf(s[mt][nt][0], C2, -mc0)); sum0 += s[mt][nt][0];
                s[mt][nt][1] = exp2f(fmaf(s[mt][nt][1], C2, -mc0)); sum0 += s[mt][nt][1];
                s[mt][nt][2] = exp2f(fmaf(s[mt][nt][2], C2, -mc1)); sum1 += s[mt][nt][2];
                s[mt][nt][3] = exp2f(fmaf(s[mt][nt][3], C2, -mc1)); sum1 += s[mt][nt][3];
            }
            sum0 += __shfl_xor_sync(0xffffffffu, sum0, 1);
            sum0 += __shfl_xor_sync(0xffffffffu, sum0, 2);
            sum1 += __shfl_xor_sync(0xffffffffu, sum1, 1);
            sum1 += __shfl_xor_sync(0xffffffffu, sum1, 2);

            l[mt][0] = l[mt][0] * a0 + sum0;
            l[mt][1] = l[mt][1] * a1 + sum1;
            m[mt][0] = nm0; m[mt][1] = nm1;
            #pragma unroll
            for (int nt = 0; nt < 8; nt++) {
                oacc[mt][nt][0] *= a0; oacc[mt][nt][1] *= a0;
                oacc[mt][nt][2] *= a1; oacc[mt][nt][3] *= a1;
            }

            // stage P (warp-private, float2)
            #pragma unroll
            for (int nt = 0; nt < 8; nt++) {
                float2 p0 = {tf32r(s[mt][nt][0]), tf32r(s[mt][nt][1])};
                float2 p1 = {tf32r(s[mt][nt][2]), tf32r(s[mt][nt][3])};
                *(float2*)&Pw[(mt * 16 + g    ) * ATP + nt * 8 + 2 * t] = p0;
                *(float2*)&Pw[(mt * 16 + g + 8) * ATP + nt * 8 + 2 * t] = p1;
            }
        }
        __syncwarp();

        // ---- O += P V : one B load feeds both mt ----
        #pragma unroll
        for (int ks = 0; ks < 8; ks++) {
            uint32_t af[2][4];
            #pragma unroll
            for (int mt = 0; mt < 2; mt++) {
                const float* pp = Pw + mt * 16 * ATP + ks * 8;
                af[mt][0] = __float_as_uint(pp[ g      * ATP + t    ]);
                af[mt][1] = __float_as_uint(pp[(g + 8) * ATP + t    ]);
                af[mt][2] = __float_as_uint(pp[ g      * ATP + t + 4]);
                af[mt][3] = __float_as_uint(pp[(g + 8) * ATP + t + 4]);
            }
            #pragma unroll
            for (int nt = 0; nt < 8; nt++) {
                const float* bp = Vt + (nt * 8 + g) * ATP + ks * 8 + t;
                uint32_t b0 = __float_as_uint(bp[0]);
                uint32_t b1 = __float_as_uint(bp[4]);
                mma_tf32(oacc[0][nt], af[0], b0, b1);
                mma_tf32(oacc[1][nt], af[1], b0, b1);
            }
        }
        __syncwarp();
    }

    // ---- epilogue ----
    #pragma unroll
    for (int mt = 0; mt < 2; mt++) {
        const float inv0 = 1.0f / l[mt][0], inv1 = 1.0f / l[mt][1];
        float* Og = O + ((size_t)b * SEQ + q0 + wid * 32 + mt * 16) * HID + h * HD;
        #pragma unroll
        for (int nt = 0; nt < 8; nt++) {
            const int col = nt * 8 + 2 * t;
            float2 v0 = {oacc[mt][nt][0] * inv0, oacc[mt][nt][1] * inv0};
            float2 v1 = {oacc[mt][nt][2] * inv1, oacc[mt][nt][3] * inv1};
            *(float2*)&Og[(size_t) g      * HID + col] = v0;
            *(float2*)&Og[(size_t)(g + 8) * HID + col] = v1;
        }
    }
}

// ===========================================================================
extern "C" void kernel_launch(void* const* d_in, const int* in_sizes, int n_in,
                              void* d_out, int out_size)
{
    const float* q   = (const float*)d_in[0];
    const float* Wq  = (const float*)d_in[1];
    const float* bq  = (const float*)d_in[2];
    const float* Wkv = (const float*)d_in[3];
    const float* bkv = (const float*)d_in[4];
    const float* Wo  = (const float*)d_in[5];
    const float* bo  = (const float*)d_in[6];
    float* out = (float*)d_out;

    void *pQ, *pK, *pV, *pO;
    cudaGetSymbolAddress(&pQ, g_Q);
    cudaGetSymbolAddress(&pK, g_K);
    cudaGetSymbolAddress(&pV, g_V);
    cudaGetSymbolAddress(&pO, g_O);
    float* gQ = (float*)pQ;
    float* gK = (float*)pK;
    float* gV = (float*)pV;
    float* gO = (float*)pO;

    cudaFuncSetAttribute(gemm_tc, cudaFuncAttributeMaxDynamicSharedMemorySize,
                         GEMM_SMEM);
    cudaFuncSetAttribute(attn_tc, cudaFuncAttributeMaxDynamicSharedMemorySize,
                         ATTN_SMEM);

    dim3 ggrid(HID / 128, MROWS / 128);

    gemm_tc<<<ggrid, 256, GEMM_SMEM>>>(q, HID, Wq, HID, bq, gQ, HID, HID);
    gemm_tc<<<ggrid, 256, GEMM_SMEM>>>(q, HID, Wkv, 2 * HID, bkv, gK, HID, HID);
    gemm_tc<<<ggrid, 256, GEMM_SMEM>>>(q, HID, Wkv + HID, 2 * HID, bkv + HID,
                                       gV, HID, HID);

    dim3 agrid(SEQ / 128, NH, BATCH);     // (16, 16, 2) = 512 CTAs
    attn_tc<<<agrid, 128, ATTN_SMEM>>>(gQ, gK, gV, gO);

    gemm_tc<<<ggrid, 256, GEMM_SMEM>>>(gO, HID, Wo, HID, bo, out, HID, HID);
}

// round 9
// speedup vs baseline: 1.0935x; 1.0935x over previous
#include <cuda_runtime.h>
#include <cstdint>

// ---------------------------------------------------------------------------
// MHA on mma.sync m16n8k8 tf32.  R9: R7 config (256 thr, 256 q rows, mt=2)
// + double-buffered K/V planes: one barrier per kv tile, staging of tile n+1
// issued between P-stage and PV so its LDG latency hides under PV mmas.
// GEMMs unchanged.
// ---------------------------------------------------------------------------

#define SEQ     2048
#define BATCH   2
#define NH      16
#define HD      64
#define HID     1024
#define MROWS   (BATCH * SEQ)   // 4096

__device__ float g_Q[MROWS * HID];
__device__ float g_K[MROWS * HID];
__device__ float g_V[MROWS * HID];
__device__ float g_O[MROWS * HID];

// ------------------------------ helpers ------------------------------------
__device__ __forceinline__ float tf32r(float f) {
    uint32_t r;
    asm("cvt.rna.tf32.f32 %0, %1;" : "=r"(r) : "f"(f));
    return __uint_as_float(r);
}

__device__ __forceinline__ void mma_tf32(float* d, const uint32_t* a,
                                         uint32_t b0, uint32_t b1) {
    asm volatile(
        "mma.sync.aligned.m16n8k8.row.col.f32.tf32.tf32.f32 "
        "{%0,%1,%2,%3}, {%4,%5,%6,%7}, {%8,%9}, {%0,%1,%2,%3};"
        : "+f"(d[0]), "+f"(d[1]), "+f"(d[2]), "+f"(d[3])
        : "r"(a[0]), "r"(a[1]), "r"(a[2]), "r"(a[3]), "r"(b0), "r"(b1));
}

// ============================ tf32 GEMM (unchanged, passing) ================
#define PADA 36
#define PADB 136
#define GEMM_SMEM ((2 * (128 * PADA + 32 * PADB)) * (int)sizeof(float))

__global__ __launch_bounds__(256) void gemm_tc(
    const float* __restrict__ A, int lda,
    const float* __restrict__ B, int ldb,
    const float* __restrict__ bias,
    float* __restrict__ C, int ldc, int K)
{
    extern __shared__ float smg[];
    float* As = smg;
    float* Bs = smg + 2 * 128 * PADA;

    const int tid  = threadIdx.x;
    const int wid  = tid >> 5, lane = tid & 31;
    const int g    = lane >> 2, t = lane & 3;
    const int wr   = wid & 1,  wc = wid >> 1;
    const int row0 = blockIdx.y * 128;
    const int col0 = blockIdx.x * 128;

    const int ar = tid >> 3, ac = (tid & 7) * 4;
    const int br = tid >> 3, bc = (tid & 7) * 4;

    const float* Ag = A + (size_t)row0 * lda;
    const float* Bg = B + col0;

    float4 ra[4], rb[4];
    const int NT = K >> 5;

    #pragma unroll
    for (int i = 0; i < 4; i++)
        ra[i] = *(const float4*)(Ag + (size_t)(ar + 32 * i) * lda + ac);
    #pragma unroll
    for (int j = 0; j < 4; j++)
        rb[j] = *(const float4*)(Bg + (size_t)br * ldb + bc + 32 * j);
    {
        #pragma unroll
        for (int i = 0; i < 4; i++) {
            float* d = As + (ar + 32 * i) * PADA + ac;
            d[0] = tf32r(ra[i].x); d[1] = tf32r(ra[i].y);
            d[2] = tf32r(ra[i].z); d[3] = tf32r(ra[i].w);
        }
        #pragma unroll
        for (int j = 0; j < 4; j++) {
            float* d = Bs + br * PADB + bc + 32 * j;
            d[0] = tf32r(rb[j].x); d[1] = tf32r(rb[j].y);
            d[2] = tf32r(rb[j].z); d[3] = tf32r(rb[j].w);
        }
    }
    __syncthreads();

    float acc[4][4][4] = {};

    for (int kt = 0; kt < NT; kt++) {
        if (kt + 1 < NT) {
            const int k0 = (kt + 1) * 32;
            #pragma unroll
            for (int i = 0; i < 4; i++)
                ra[i] = *(const float4*)(Ag + (size_t)(ar + 32 * i) * lda + k0 + ac);
            #pragma unroll
            for (int j = 0; j < 4; j++)
                rb[j] = *(const float4*)(Bg + (size_t)(k0 + br) * ldb + bc + 32 * j);
        }

        const float* Ac = As + (kt & 1) * 128 * PADA;
        const float* Bc = Bs + (kt & 1) * 32 * PADB;

        #pragma unroll
        for (int kk = 0; kk < 4; kk++) {
            uint32_t af[4][4];
            #pragma unroll
            for (int mt = 0; mt < 4; mt++) {
                const float* ap = Ac + (wr * 64 + mt * 16) * PADA + kk * 8;
                af[mt][0] = __float_as_uint(ap[ g      * PADA + t    ]);
                af[mt][1] = __float_as_uint(ap[(g + 8) * PADA + t    ]);
                af[mt][2] = __float_as_uint(ap[ g      * PADA + t + 4]);
                af[mt][3] = __float_as_uint(ap[(g + 8) * PADA + t + 4]);
            }
            #pragma unroll
            for (int nt = 0; nt < 4; nt++) {
                const float* bp = Bc + kk * 8 * PADB + wc * 32 + nt * 8 + g;
                uint32_t b0 = __float_as_uint(bp[ t      * PADB]);
                uint32_t b1 = __float_as_uint(bp[(t + 4) * PADB]);
                #pragma unroll
                for (int mt = 0; mt < 4; mt++)
                    mma_tf32(acc[mt][nt], af[mt], b0, b1);
            }
        }

        if (kt + 1 < NT) {
            __syncthreads();
            float* Ad = As + ((kt + 1) & 1) * 128 * PADA;
            float* Bd = Bs + ((kt + 1) & 1) * 32 * PADB;
            #pragma unroll
            for (int i = 0; i < 4; i++) {
                float* d = Ad + (ar + 32 * i) * PADA + ac;
                d[0] = tf32r(ra[i].x); d[1] = tf32r(ra[i].y);
                d[2] = tf32r(ra[i].z); d[3] = tf32r(ra[i].w);
            }
            #pragma unroll
            for (int j = 0; j < 4; j++) {
                float* d = Bd + br * PADB + bc + 32 * j;
                d[0] = tf32r(rb[j].x); d[1] = tf32r(rb[j].y);
                d[2] = tf32r(rb[j].z); d[3] = tf32r(rb[j].w);
            }
            __syncthreads();
        }
    }

    #pragma unroll
    for (int mt = 0; mt < 4; mt++) {
        const int row = row0 + wr * 64 + mt * 16 + g;
        #pragma unroll
        for (int nt = 0; nt < 4; nt++) {
            const int col = col0 + wc * 32 + nt * 8 + 2 * t;
            float2 bb = *(const float2*)&bias[col];
            float2 v0 = {acc[mt][nt][0] + bb.x, acc[mt][nt][1] + bb.y};
            float2 v1 = {acc[mt][nt][2] + bb.x, acc[mt][nt][3] + bb.y};
            *(float2*)&C[(size_t)row * ldc + col]       = v0;
            *(float2*)&C[(size_t)(row + 8) * ldc + col] = v1;
        }
    }
}

// ============================ attention ====================================
// 256 q rows/CTA, 8 warps x 32 q rows (mt=2). Double-buffered K/V planes:
// one __syncthreads per kv tile; next tile staged between P-stage and PV.
#define ATP 68
#define KVPLANE (64 * ATP)
#define ATTN_SMEM ((4 * KVPLANE + 256 * ATP) * (int)sizeof(float))   // 139264

__global__ __launch_bounds__(256, 1) void attn_tc(
    const float* __restrict__ Q,
    const float* __restrict__ Kin,
    const float* __restrict__ V,
    float* __restrict__ O)
{
    extern __shared__ float sma[];
    float* Ks = sma;                        // [2][j][d] planes
    float* Vt = sma + 2 * KVPLANE;          // [2][d][j] planes
    float* Ps = sma + 4 * KVPLANE;          // Q stage (256xATP), then P slabs

    const int tid  = threadIdx.x;
    const int wid  = tid >> 5, lane = tid & 31;
    const int g    = lane >> 2, t = lane & 3;
    const int b    = blockIdx.z;
    const int h    = blockIdx.y;
    const int q0   = blockIdx.x * 256;
    const float C2 = 0.125f * 1.44269504088896340736f;   // scale*log2(e)

    const float* Qg = Q   + ((size_t)b * SEQ + q0) * HID + h * HD;
    const float* Kg = Kin + (size_t)b * SEQ * HID + h * HD;
    const float* Vg = V   + (size_t)b * SEQ * HID + h * HD;

    // staging maps (256 threads; 4 float4 each for K and V)
    const int jk = tid >> 2, dk = (tid & 3) * 16;    // K: [j][d]
    const int jv = tid & 63, dv = (tid >> 6) * 16;   // V: write [d][j]

    // ---- stage Q (tf32) into Ps, preload fragments ----
    for (int idx = tid; idx < 256 * 16; idx += 256) {
        const int r = idx >> 4, d4 = (idx & 15) * 4;
        float4 v = *(const float4*)(Qg + (size_t)r * HID + d4);
        float* d = Ps + r * ATP + d4;
        d[0] = tf32r(v.x); d[1] = tf32r(v.y); d[2] = tf32r(v.z); d[3] = tf32r(v.w);
    }
    __syncthreads();

    uint32_t qf[2][8][4];
    #pragma unroll
    for (int mt = 0; mt < 2; mt++) {
        #pragma unroll
        for (int ks = 0; ks < 8; ks++) {
            const float* qp = Ps + (wid * 32 + mt * 16) * ATP + ks * 8;
            qf[mt][ks][0] = __float_as_uint(qp[ g      * ATP + t    ]);
            qf[mt][ks][1] = __float_as_uint(qp[(g + 8) * ATP + t    ]);
            qf[mt][ks][2] = __float_as_uint(qp[ g      * ATP + t + 4]);
            qf[mt][ks][3] = __float_as_uint(qp[(g + 8) * ATP + t + 4]);
        }
    }
    __syncthreads();

    // ---- prologue: stage kv tile 0 into plane 0 ----
    {
        float* Kd = Ks;
        float* Vd = Vt;
        #pragma unroll
        for (int i = 0; i < 4; i++) {
            float4 kv4 = *(const float4*)(Kg + (size_t)jk * HID + dk + 4 * i);
            float* kd = Kd + jk * ATP + dk + 4 * i;
            kd[0] = tf32r(kv4.x); kd[1] = tf32r(kv4.y);
            kd[2] = tf32r(kv4.z); kd[3] = tf32r(kv4.w);
            float4 vv = *(const float4*)(Vg + (size_t)jv * HID + dv + 4 * i);
            const int d = dv + 4 * i;
            Vd[(d + 0) * ATP + jv] = tf32r(vv.x);
            Vd[(d + 1) * ATP + jv] = tf32r(vv.y);
            Vd[(d + 2) * ATP + jv] = tf32r(vv.z);
            Vd[(d + 3) * ATP + jv] = tf32r(vv.w);
        }
    }

    float oacc[2][8][4] = {};
    float m[2][2], l[2][2];
    #pragma unroll
    for (int mt = 0; mt < 2; mt++) {
        m[mt][0] = -1e30f; m[mt][1] = -1e30f;
        l[mt][0] = 0.0f;   l[mt][1] = 0.0f;
    }

    float* Pw = Ps + wid * 32 * ATP;

    for (int kv0 = 0; kv0 < SEQ; kv0 += 64) {
        const int cur = (kv0 >> 6) & 1;
        const bool more = (kv0 + 64 < SEQ);
        // barrier: prior tile's K/V reads done (plane cur^1 free to overwrite),
        // and plane cur (staged last tile) visible.
        __syncthreads();

        const float* KC = Ks + cur * KVPLANE;
        const float* VC = Vt + cur * KVPLANE;

        // ---- S = Q K^T : one B load feeds both mt ----
        float s[2][8][4] = {};
        #pragma unroll
        for (int nt = 0; nt < 8; nt++) {
            #pragma unroll
            for (int ks = 0; ks < 8; ks++) {
                const float* bp = KC + (nt * 8 + g) * ATP + ks * 8 + t;
                uint32_t b0 = __float_as_uint(bp[0]);
                uint32_t b1 = __float_as_uint(bp[4]);
                mma_tf32(s[0][nt], qf[0][ks], b0, b1);
                mma_tf32(s[1][nt], qf[1][ks], b0, b1);
            }
        }

        // ---- online softmax per mt (raw-score max, exp2-folded) ----
        #pragma unroll
        for (int mt = 0; mt < 2; mt++) {
            float rm0 = -1e30f, rm1 = -1e30f;
            #pragma unroll
            for (int nt = 0; nt < 8; nt++) {
                rm0 = fmaxf(rm0, fmaxf(s[mt][nt][0], s[mt][nt][1]));
                rm1 = fmaxf(rm1, fmaxf(s[mt][nt][2], s[mt][nt][3]));
            }
            rm0 = fmaxf(rm0, __shfl_xor_sync(0xffffffffu, rm0, 1));
            rm0 = fmaxf(rm0, __shfl_xor_sync(0xffffffffu, rm0, 2));
            rm1 = fmaxf(rm1, __shfl_xor_sync(0xffffffffu, rm1, 1));
            rm1 = fmaxf(rm1, __shfl_xor_sync(0xffffffffu, rm1, 2));

            const float nm0 = fmaxf(m[mt][0], rm0), nm1 = fmaxf(m[mt][1], rm1);
            const float a0 = exp2f((m[mt][0] - nm0) * C2);
            const float a1 = exp2f((m[mt][1] - nm1) * C2);
            const float mc0 = nm0 * C2, mc1 = nm1 * C2;
            float sum0 = 0.0f, sum1 = 0.0f;
            #pragma unroll
            for (int nt = 0; nt < 8; nt++) {
                s[mt][nt][0] = exp2f(fmaf(s[mt][nt][0], C2, -mc0)); sum0 += s[mt][nt][0];
                s[mt][nt][1] = exp2f(fmaf(s[mt][nt][1], C2, -mc0)); sum0 += s[mt][nt][1];
                s[mt][nt][2] = exp2f(fmaf(s[mt][nt][2], C2, -mc1)); sum1 += s[mt][nt][2];
                s[mt][nt][3] = exp2f(fmaf(s[mt][nt][3], C2, -mc1)); sum1 += s[mt][nt][3];
            }
            sum0 += __shfl_xor_sync(0xffffffffu, sum0, 1);
            sum0 += __shfl_xor_sync(0xffffffffu, sum0, 2);
            sum1 += __shfl_xor_sync(0xffffffffu, sum1, 1);
            sum1 += __shfl_xor_sync(0xffffffffu, sum1, 2);

            l[mt][0] = l[mt][0] * a0 + sum0;
            l[mt][1] = l[mt][1] * a1 + sum1;
            m[mt][0] = nm0; m[mt][1] = nm1;
            #pragma unroll
            for (int nt = 0; nt < 8; nt++) {
                oacc[mt][nt][0] *= a0; oacc[mt][nt][1] *= a0;
                oacc[mt][nt][2] *= a1; oacc[mt][nt][3] *= a1;
            }

            // stage P (warp-private, float2)
            #pragma unroll
            for (int nt = 0; nt < 8; nt++) {
                float2 p0 = {tf32r(s[mt][nt][0]), tf32r(s[mt][nt][1])};
                float2 p1 = {tf32r(s[mt][nt][2]), tf32r(s[mt][nt][3])};
                *(float2*)&Pw[(mt * 16 + g    ) * ATP + nt * 8 + 2 * t] = p0;
                *(float2*)&Pw[(mt * 16 + g + 8) * ATP + nt * 8 + 2 * t] = p1;
            }
        }
        __syncwarp();

        // ---- stage next kv tile into the other plane (overlaps with PV) ----
        if (more) {
            float* Kd = Ks + (cur ^ 1) * KVPLANE;
            float* Vd = Vt + (cur ^ 1) * KVPLANE;
            const int nj = kv0 + 64;
            #pragma unroll
            for (int i = 0; i < 4; i++) {
                float4 kv4 = *(const float4*)(Kg + (size_t)(nj + jk) * HID + dk + 4 * i);
                float* kd = Kd + jk * ATP + dk + 4 * i;
                kd[0] = tf32r(kv4.x); kd[1] = tf32r(kv4.y);
                kd[2] = tf32r(kv4.z); kd[3] = tf32r(kv4.w);
                float4 vv = *(const float4*)(Vg + (size_t)(nj + jv) * HID + dv + 4 * i);
                const int d = dv + 4 * i;
                Vd[(d + 0) * ATP + jv] = tf32r(vv.x);
                Vd[(d + 1) * ATP + jv] = tf32r(vv.y);
                Vd[(d + 2) * ATP + jv] = tf32r(vv.z);
                Vd[(d + 3) * ATP + jv] = tf32r(vv.w);
            }
        }

        // ---- O += P V : one B load feeds both mt ----
        #pragma unroll
        for (int ks = 0; ks < 8; ks++) {
            uint32_t af[2][4];
            #pragma unroll
            for (int mt = 0; mt < 2; mt++) {
                const float* pp = Pw + mt * 16 * ATP + ks * 8;
                af[mt][0] = __float_as_uint(pp[ g      * ATP + t    ]);
                af[mt][1] = __float_as_uint(pp[(g + 8) * ATP + t    ]);
                af[mt][2] = __float_as_uint(pp[ g      * ATP + t + 4]);
                af[mt][3] = __float_as_uint(pp[(g + 8) * ATP + t + 4]);
            }
            #pragma unroll
            for (int nt = 0; nt < 8; nt++) {
                const float* bp = VC + (nt * 8 + g) * ATP + ks * 8 + t;
                uint32_t b0 = __float_as_uint(bp[0]);
                uint32_t b1 = __float_as_uint(bp[4]);
                mma_tf32(oacc[0][nt], af[0], b0, b1);
                mma_tf32(oacc[1][nt], af[1], b0, b1);
            }
        }
        __syncwarp();
    }

    // ---- epilogue ----
    #pragma unroll
    for (int mt = 0; mt < 2; mt++) {
        const float inv0 = 1.0f / l[mt][0], inv1 = 1.0f / l[mt][1];
        float* Og = O + ((size_t)b * SEQ + q0 + wid * 32 + mt * 16) * HID + h * HD;
        #pragma unroll
        for (int nt = 0; nt < 8; nt++) {
            const int col = nt * 8 + 2 * t;
            float2 v0 = {oacc[mt][nt][0] * inv0, oacc[mt][nt][1] * inv0};
            float2 v1 = {oacc[mt][nt][2] * inv1, oacc[mt][nt][3] * inv1};
            *(float2*)&Og[(size_t) g      * HID + col] = v0;
            *(float2*)&Og[(size_t)(g + 8) * HID + col] = v1;
        }
    }
}

// ===========================================================================
extern "C" void kernel_launch(void* const* d_in, const int* in_sizes, int n_in,
                              void* d_out, int out_size)
{
    const float* q   = (const float*)d_in[0];
    const float* Wq  = (const float*)d_in[1];
    const float* bq  = (const float*)d_in[2];
    const float* Wkv = (const float*)d_in[3];
    const float* bkv = (const float*)d_in[4];
    const float* Wo  = (const float*)d_in[5];
    const float* bo  = (const float*)d_in[6];
    float* out = (float*)d_out;

    void *pQ, *pK, *pV, *pO;
    cudaGetSymbolAddress(&pQ, g_Q);
    cudaGetSymbolAddress(&pK, g_K);
    cudaGetSymbolAddress(&pV, g_V);
    cudaGetSymbolAddress(&pO, g_O);
    float* gQ = (float*)pQ;
    float* gK = (float*)pK;
    float* gV = (float*)pV;
    float* gO = (float*)pO;

    cudaFuncSetAttribute(gemm_tc, cudaFuncAttributeMaxDynamicSharedMemorySize,
                         GEMM_SMEM);
    cudaFuncSetAttribute(attn_tc, cudaFuncAttributeMaxDynamicSharedMemorySize,
                         ATTN_SMEM);

    dim3 ggrid(HID / 128, MROWS / 128);

    gemm_tc<<<ggrid, 256, GEMM_SMEM>>>(q, HID, Wq, HID, bq, gQ, HID, HID);
    gemm_tc<<<ggrid, 256, GEMM_SMEM>>>(q, HID, Wkv, 2 * HID, bkv, gK, HID, HID);
    gemm_tc<<<ggrid, 256, GEMM_SMEM>>>(q, HID, Wkv + HID, 2 * HID, bkv + HID,
                                       gV, HID, HID);

    dim3 agrid(SEQ / 256, NH, BATCH);     // (8, 16, 2) = 256 CTAs
    attn_tc<<<agrid, 256, ATTN_SMEM>>>(gQ, gK, gV, gO);

    gemm_tc<<<ggrid, 256, GEMM_SMEM>>>(gO, HID, Wo, HID, bo, out, HID, HID);
}

// round 10
// speedup vs baseline: 1.3789x; 1.2611x over previous
#include <cuda_runtime.h>
#include <cuda_fp16.h>
#include <cstdint>

// ---------------------------------------------------------------------------
// MHA.  R10: attention moved to mma.sync m16n8k16 fp16 (same 10-bit mantissa
// as tf32, half the instructions/LDS/staging per MAC).  GEMMs stay tf32.
// R7 two-barrier tile structure (measured best).
// ---------------------------------------------------------------------------

#define SEQ     2048
#define BATCH   2
#define NH      16
#define HD      64
#define HID     1024
#define MROWS   (BATCH * SEQ)   // 4096

__device__ float g_Q[MROWS * HID];
__device__ float g_K[MROWS * HID];
__device__ float g_V[MROWS * HID];
__device__ float g_O[MROWS * HID];

// ------------------------------ helpers ------------------------------------
__device__ __forceinline__ float tf32r(float f) {
    uint32_t r;
    asm("cvt.rna.tf32.f32 %0, %1;" : "=r"(r) : "f"(f));
    return __uint_as_float(r);
}

__device__ __forceinline__ uint32_t packh2(float a, float b) {
    __half2 h = __floats2half2_rn(a, b);
    return *(uint32_t*)&h;
}

__device__ __forceinline__ void mma_tf32(float* d, const uint32_t* a,
                                         uint32_t b0, uint32_t b1) {
    asm volatile(
        "mma.sync.aligned.m16n8k8.row.col.f32.tf32.tf32.f32 "
        "{%0,%1,%2,%3}, {%4,%5,%6,%7}, {%8,%9}, {%0,%1,%2,%3};"
        : "+f"(d[0]), "+f"(d[1]), "+f"(d[2]), "+f"(d[3])
        : "r"(a[0]), "r"(a[1]), "r"(a[2]), "r"(a[3]), "r"(b0), "r"(b1));
}

__device__ __forceinline__ void mma_f16(float* d, const uint32_t* a,
                                        uint32_t b0, uint32_t b1) {
    asm volatile(
        "mma.sync.aligned.m16n8k16.row.col.f32.f16.f16.f32 "
        "{%0,%1,%2,%3}, {%4,%5,%6,%7}, {%8,%9}, {%0,%1,%2,%3};"
        : "+f"(d[0]), "+f"(d[1]), "+f"(d[2]), "+f"(d[3])
        : "r"(a[0]), "r"(a[1]), "r"(a[2]), "r"(a[3]), "r"(b0), "r"(b1));
}

// ============================ tf32 GEMM (unchanged, passing) ================
#define PADA 36
#define PADB 136
#define GEMM_SMEM ((2 * (128 * PADA + 32 * PADB)) * (int)sizeof(float))

__global__ __launch_bounds__(256) void gemm_tc(
    const float* __restrict__ A, int lda,
    const float* __restrict__ B, int ldb,
    const float* __restrict__ bias,
    float* __restrict__ C, int ldc, int K)
{
    extern __shared__ float smg[];
    float* As = smg;
    float* Bs = smg + 2 * 128 * PADA;

    const int tid  = threadIdx.x;
    const int wid  = tid >> 5, lane = tid & 31;
    const int g    = lane >> 2, t = lane & 3;
    const int wr   = wid & 1,  wc = wid >> 1;
    const int row0 = blockIdx.y * 128;
    const int col0 = blockIdx.x * 128;

    const int ar = tid >> 3, ac = (tid & 7) * 4;
    const int br = tid >> 3, bc = (tid & 7) * 4;

    const float* Ag = A + (size_t)row0 * lda;
    const float* Bg = B + col0;

    float4 ra[4], rb[4];
    const int NT = K >> 5;

    #pragma unroll
    for (int i = 0; i < 4; i++)
        ra[i] = *(const float4*)(Ag + (size_t)(ar + 32 * i) * lda + ac);
    #pragma unroll
    for (int j = 0; j < 4; j++)
        rb[j] = *(const float4*)(Bg + (size_t)br * ldb + bc + 32 * j);
    {
        #pragma unroll
        for (int i = 0; i < 4; i++) {
            float* d = As + (ar + 32 * i) * PADA + ac;
            d[0] = tf32r(ra[i].x); d[1] = tf32r(ra[i].y);
            d[2] = tf32r(ra[i].z); d[3] = tf32r(ra[i].w);
        }
        #pragma unroll
        for (int j = 0; j < 4; j++) {
            float* d = Bs + br * PADB + bc + 32 * j;
            d[0] = tf32r(rb[j].x); d[1] = tf32r(rb[j].y);
            d[2] = tf32r(rb[j].z); d[3] = tf32r(rb[j].w);
        }
    }
    __syncthreads();

    float acc[4][4][4] = {};

    for (int kt = 0; kt < NT; kt++) {
        if (kt + 1 < NT) {
            const int k0 = (kt + 1) * 32;
            #pragma unroll
            for (int i = 0; i < 4; i++)
                ra[i] = *(const float4*)(Ag + (size_t)(ar + 32 * i) * lda + k0 + ac);
            #pragma unroll
            for (int j = 0; j < 4; j++)
                rb[j] = *(const float4*)(Bg + (size_t)(k0 + br) * ldb + bc + 32 * j);
        }

        const float* Ac = As + (kt & 1) * 128 * PADA;
        const float* Bc = Bs + (kt & 1) * 32 * PADB;

        #pragma unroll
        for (int kk = 0; kk < 4; kk++) {
            uint32_t af[4][4];
            #pragma unroll
            for (int mt = 0; mt < 4; mt++) {
                const float* ap = Ac + (wr * 64 + mt * 16) * PADA + kk * 8;
                af[mt][0] = __float_as_uint(ap[ g      * PADA + t    ]);
                af[mt][1] = __float_as_uint(ap[(g + 8) * PADA + t    ]);
                af[mt][2] = __float_as_uint(ap[ g      * PADA + t + 4]);
                af[mt][3] = __float_as_uint(ap[(g + 8) * PADA + t + 4]);
            }
            #pragma unroll
            for (int nt = 0; nt < 4; nt++) {
                const float* bp = Bc + kk * 8 * PADB + wc * 32 + nt * 8 + g;
                uint32_t b0 = __float_as_uint(bp[ t      * PADB]);
                uint32_t b1 = __float_as_uint(bp[(t + 4) * PADB]);
                #pragma unroll
                for (int mt = 0; mt < 4; mt++)
                    mma_tf32(acc[mt][nt], af[mt], b0, b1);
            }
        }

        if (kt + 1 < NT) {
            __syncthreads();
            float* Ad = As + ((kt + 1) & 1) * 128 * PADA;
            float* Bd = Bs + ((kt + 1) & 1) * 32 * PADB;
            #pragma unroll
            for (int i = 0; i < 4; i++) {
                float* d = Ad + (ar + 32 * i) * PADA + ac;
                d[0] = tf32r(ra[i].x); d[1] = tf32r(ra[i].y);
                d[2] = tf32r(ra[i].z); d[3] = tf32r(ra[i].w);
            }
            #pragma unroll
            for (int j = 0; j < 4; j++) {
                float* d = Bd + br * PADB + bc + 32 * j;
                d[0] = tf32r(rb[j].x); d[1] = tf32r(rb[j].y);
                d[2] = tf32r(rb[j].z); d[3] = tf32r(rb[j].w);
            }
            __syncthreads();
        }
    }

    #pragma unroll
    for (int mt = 0; mt < 4; mt++) {
        const int row = row0 + wr * 64 + mt * 16 + g;
        #pragma unroll
        for (int nt = 0; nt < 4; nt++) {
            const int col = col0 + wc * 32 + nt * 8 + 2 * t;
            float2 bb = *(const float2*)&bias[col];
            float2 v0 = {acc[mt][nt][0] + bb.x, acc[mt][nt][1] + bb.y};
            float2 v1 = {acc[mt][nt][2] + bb.x, acc[mt][nt][3] + bb.y};
            *(float2*)&C[(size_t)row * ldc + col]       = v0;
            *(float2*)&C[(size_t)(row + 8) * ldc + col] = v1;
        }
    }
}

// ============================ attention (fp16 mma) =========================
// 256 q rows/CTA, 8 warps x 32 q rows (mt=2), m16n8k16 fp16.
// smem (uint32 units): K 64x36, V(pair-interleaved) 32x72, Q/P 256x36.
#define PADK 36
#define PADV 72
#define PADQ 36
#define ATTN_SMEM ((64*PADK + 32*PADV + 256*PADQ) * 4)   // 55296 bytes

__global__ __launch_bounds__(256, 1) void attn_tc(
    const float* __restrict__ Q,
    const float* __restrict__ Kin,
    const float* __restrict__ V,
    float* __restrict__ O)
{
    extern __shared__ uint32_t smu[];
    uint32_t* ksm = smu;                      // [j][d2]   64 x PADK
    uint32_t* vsm = smu + 64 * PADK;          // [j2][d]   32 x PADV
    uint32_t* qps = smu + 64 * PADK + 32 * PADV;   // Q stage / P slabs 256 x PADQ

    const int tid  = threadIdx.x;
    const int wid  = tid >> 5, lane = tid & 31;
    const int g    = lane >> 2, t = lane & 3;
    const int b    = blockIdx.z;
    const int h    = blockIdx.y;
    const int q0   = blockIdx.x * 256;
    const float C2 = 0.125f * 1.44269504088896340736f;   // scale*log2(e)

    const float* Qg = Q   + ((size_t)b * SEQ + q0) * HID + h * HD;
    const float* Kg = Kin + (size_t)b * SEQ * HID + h * HD;
    const float* Vg = V   + (size_t)b * SEQ * HID + h * HD;

    // ---- stage Q as fp16 pairs into qps ----
    for (int idx = tid; idx < 1024; idx += 256) {
        const int r = idx >> 2, sg = (idx & 3) * 8;   // sg: u32 col base
        const float* src = Qg + (size_t)r * HID + sg * 2;
        uint32_t tmp[8];
        #pragma unroll
        for (int i = 0; i < 4; i++) {
            float4 v = *(const float4*)(src + 4 * i);
            tmp[2 * i + 0] = packh2(v.x, v.y);
            tmp[2 * i + 1] = packh2(v.z, v.w);
        }
        *(uint4*)&qps[r * PADQ + sg]     = *(uint4*)&tmp[0];
        *(uint4*)&qps[r * PADQ + sg + 4] = *(uint4*)&tmp[4];
    }
    __syncthreads();

    // ---- preload Q fragments: qf[mt][ks][4], ks = 0..3 (k16 blocks) ----
    uint32_t qf[2][4][4];
    #pragma unroll
    for (int mt = 0; mt < 2; mt++) {
        const int r0 = (wid * 32 + mt * 16 + g) * PADQ;
        const int r1 = r0 + 8 * PADQ;
        #pragma unroll
        for (int ks = 0; ks < 4; ks++) {
            qf[mt][ks][0] = qps[r0 + ks * 8 + t    ];
            qf[mt][ks][1] = qps[r1 + ks * 8 + t    ];
            qf[mt][ks][2] = qps[r0 + ks * 8 + t + 4];
            qf[mt][ks][3] = qps[r1 + ks * 8 + t + 4];
        }
    }
    __syncthreads();

    float oacc[2][8][4] = {};
    float m[2][2], l[2][2];
    #pragma unroll
    for (int mt = 0; mt < 2; mt++) {
        m[mt][0] = -1e30f; m[mt][1] = -1e30f;
        l[mt][0] = 0.0f;   l[mt][1] = 0.0f;
    }

    // staging maps
    const int jk = tid >> 2, ck = (tid & 3) * 8;     // K: row jk, u32 cols ck..ck+7
    const int pv = tid >> 3, cv = (tid & 7) * 8;     // V: pair-row pv, d cols cv..cv+7

    uint32_t* Pw = qps + wid * 32 * PADQ;

    for (int kv0 = 0; kv0 < SEQ; kv0 += 64) {
        __syncthreads();   // prior tile's consumers done

        // ---- stage K (fp16 pairs along d) ----
        {
            const float* src = Kg + (size_t)(kv0 + jk) * HID + ck * 2;
            uint32_t tmp[8];
            #pragma unroll
            for (int i = 0; i < 4; i++) {
                float4 v = *(const float4*)(src + 4 * i);
                tmp[2 * i + 0] = packh2(v.x, v.y);
                tmp[2 * i + 1] = packh2(v.z, v.w);
            }
            *(uint4*)&ksm[jk * PADK + ck]     = *(uint4*)&tmp[0];
            *(uint4*)&ksm[jk * PADK + ck + 4] = *(uint4*)&tmp[4];
        }
        // ---- stage V pair-interleaved: vsm[j/2][d] = {V[2j][d], V[2j+1][d]} ----
        {
            const float* s0 = Vg + (size_t)(kv0 + 2 * pv)     * HID + cv;
            const float* s1 = Vg + (size_t)(kv0 + 2 * pv + 1) * HID + cv;
            float4 a0 = *(const float4*)(s0);
            float4 a1 = *(const float4*)(s0 + 4);
            float4 b0 = *(const float4*)(s1);
            float4 b1 = *(const float4*)(s1 + 4);
            uint32_t tmp[8];
            tmp[0] = packh2(a0.x, b0.x); tmp[1] = packh2(a0.y, b0.y);
            tmp[2] = packh2(a0.z, b0.z); tmp[3] = packh2(a0.w, b0.w);
            tmp[4] = packh2(a1.x, b1.x); tmp[5] = packh2(a1.y, b1.y);
            tmp[6] = packh2(a1.z, b1.z); tmp[7] = packh2(a1.w, b1.w);
            *(uint4*)&vsm[pv * PADV + cv]     = *(uint4*)&tmp[0];
            *(uint4*)&vsm[pv * PADV + cv + 4] = *(uint4*)&tmp[4];
        }
        __syncthreads();

        // ---- S = Q K^T : 64 mmas/warp (k16), one B load feeds both mt ----
        float s[2][8][4] = {};
        #pragma unroll
        for (int nt = 0; nt < 8; nt++) {
            const uint32_t* kp = ksm + (nt * 8 + g) * PADK;
            #pragma unroll
            for (int ks = 0; ks < 4; ks++) {
                uint32_t b0 = kp[ks * 8 + t];
                uint32_t b1 = kp[ks * 8 + t + 4];
                mma_f16(s[0][nt], qf[0][ks], b0, b1);
                mma_f16(s[1][nt], qf[1][ks], b0, b1);
            }
        }

        // ---- online softmax per mt (raw-score max, exp2-folded) ----
        #pragma unroll
        for (int mt = 0; mt < 2; mt++) {
            float rm0 = -1e30f, rm1 = -1e30f;
            #pragma unroll
            for (int nt = 0; nt < 8; nt++) {
                rm0 = fmaxf(rm0, fmaxf(s[mt][nt][0], s[mt][nt][1]));
                rm1 = fmaxf(rm1, fmaxf(s[mt][nt][2], s[mt][nt][3]));
            }
            rm0 = fmaxf(rm0, __shfl_xor_sync(0xffffffffu, rm0, 1));
            rm0 = fmaxf(rm0, __shfl_xor_sync(0xffffffffu, rm0, 2));
            rm1 = fmaxf(rm1, __shfl_xor_sync(0xffffffffu, rm1, 1));
            rm1 = fmaxf(rm1, __shfl_xor_sync(0xffffffffu, rm1, 2));

            const float nm0 = fmaxf(m[mt][0], rm0), nm1 = fmaxf(m[mt][1], rm1);
            const float a0 = exp2f((m[mt][0] - nm0) * C2);
            const float a1 = exp2f((m[mt][1] - nm1) * C2);
            const float mc0 = nm0 * C2, mc1 = nm1 * C2;
            float sum0 = 0.0f, sum1 = 0.0f;
            #pragma unroll
            for (int nt = 0; nt < 8; nt++) {
                s[mt][nt][0] = exp2f(fmaf(s[mt][nt][0], C2, -mc0)); sum0 += s[mt][nt][0];
                s[mt][nt][1] = exp2f(fmaf(s[mt][nt][1], C2, -mc0)); sum0 += s[mt][nt][1];
                s[mt][nt][2] = exp2f(fmaf(s[mt][nt][2], C2, -mc1)); sum1 += s[mt][nt][2];
                s[mt][nt][3] = exp2f(fmaf(s[mt][nt][3], C2, -mc1)); sum1 += s[mt][nt][3];
            }
            sum0 += __shfl_xor_sync(0xffffffffu, sum0, 1);
            sum0 += __shfl_xor_sync(0xffffffffu, sum0, 2);
            sum1 += __shfl_xor_sync(0xffffffffu, sum1, 1);
            sum1 += __shfl_xor_sync(0xffffffffu, sum1, 2);

            l[mt][0] = l[mt][0] * a0 + sum0;
            l[mt][1] = l[mt][1] * a1 + sum1;
            m[mt][0] = nm0; m[mt][1] = nm1;
            #pragma unroll
            for (int nt = 0; nt < 8; nt++) {
                oacc[mt][nt][0] *= a0; oacc[mt][nt][1] *= a0;
                oacc[mt][nt][2] *= a1; oacc[mt][nt][3] *= a1;
            }

            // stage P as fp16x2 (cols 2t,2t+1 are the lane's acc pair)
            #pragma unroll
            for (int nt = 0; nt < 8; nt++) {
                Pw[(mt * 16 + g    ) * PADQ + nt * 4 + t] = packh2(s[mt][nt][0], s[mt][nt][1]);
                Pw[(mt * 16 + g + 8) * PADQ + nt * 4 + t] = packh2(s[mt][nt][2], s[mt][nt][3]);
            }
        }
        __syncwarp();

        // ---- O += P V : 64 mmas/warp (k16) ----
        #pragma unroll
        for (int ks = 0; ks < 4; ks++) {
            uint32_t af[2][4];
            #pragma unroll
            for (int mt = 0; mt < 2; mt++) {
                const uint32_t* pp = Pw + (mt * 16 + g) * PADQ;
                af[mt][0] = pp[ks * 8 + t];
                af[mt][1] = pp[8 * PADQ + ks * 8 + t];
                af[mt][2] = pp[ks * 8 + t + 4];
                af[mt][3] = pp[8 * PADQ + ks * 8 + t + 4];
            }
            #pragma unroll
            for (int nt = 0; nt < 8; nt++) {
                uint32_t b0 = vsm[(ks * 8 + t    ) * PADV + nt * 8 + g];
                uint32_t b1 = vsm[(ks * 8 + t + 4) * PADV + nt * 8 + g];
                mma_f16(oacc[0][nt], af[0], b0, b1);
                mma_f16(oacc[1][nt], af[1], b0, b1);
            }
        }
        __syncwarp();
    }

    // ---- epilogue ----
    #pragma unroll
    for (int mt = 0; mt < 2; mt++) {
        const float inv0 = 1.0f / l[mt][0], inv1 = 1.0f / l[mt][1];
        float* Og = O + ((size_t)b * SEQ + q0 + wid * 32 + mt * 16) * HID + h * HD;
        #pragma unroll
        for (int nt = 0; nt < 8; nt++) {
            const int col = nt * 8 + 2 * t;
            float2 v0 = {oacc[mt][nt][0] * inv0, oacc[mt][nt][1] * inv0};
            float2 v1 = {oacc[mt][nt][2] * inv1, oacc[mt][nt][3] * inv1};
            *(float2*)&Og[(size_t) g      * HID + col] = v0;
            *(float2*)&Og[(size_t)(g + 8) * HID + col] = v1;
        }
    }
}

// ===========================================================================
extern "C" void kernel_launch(void* const* d_in, const int* in_sizes, int n_in,
                              void* d_out, int out_size)
{
    const float* q   = (const float*)d_in[0];
    const float* Wq  = (const float*)d_in[1];
    const float* bq  = (const float*)d_in[2];
    const float* Wkv = (const float*)d_in[3];
    const float* bkv = (const float*)d_in[4];
    const float* Wo  = (const float*)d_in[5];
    const float* bo  = (const float*)d_in[6];
    float* out = (float*)d_out;

    void *pQ, *pK, *pV, *pO;
    cudaGetSymbolAddress(&pQ, g_Q);
    cudaGetSymbolAddress(&pK, g_K);
    cudaGetSymbolAddress(&pV, g_V);
    cudaGetSymbolAddress(&pO, g_O);
    float* gQ = (float*)pQ;
    float* gK = (float*)pK;
    float* gV = (float*)pV;
    float* gO = (float*)pO;

    cudaFuncSetAttribute(gemm_tc, cudaFuncAttributeMaxDynamicSharedMemorySize,
                         GEMM_SMEM);
    cudaFuncSetAttribute(attn_tc, cudaFuncAttributeMaxDynamicSharedMemorySize,
                         ATTN_SMEM);

    dim3 ggrid(HID / 128, MROWS / 128);

    gemm_tc<<<ggrid, 256, GEMM_SMEM>>>(q, HID, Wq, HID, bq, gQ, HID, HID);
    gemm_tc<<<ggrid, 256, GEMM_SMEM>>>(q, HID, Wkv, 2 * HID, bkv, gK, HID, HID);
    gemm_tc<<<ggrid, 256, GEMM_SMEM>>>(q, HID, Wkv + HID, 2 * HID, bkv + HID,
                                       gV, HID, HID);

    dim3 agrid(SEQ / 256, NH, BATCH);     // (8, 16, 2) = 256 CTAs
    attn_tc<<<agrid, 256, ATTN_SMEM>>>(gQ, gK, gV, gO);

    gemm_tc<<<ggrid, 256, GEMM_SMEM>>>(gO, HID, Wo, HID, bo, out, HID, HID);
}

// round 11
// speedup vs baseline: 1.4251x; 1.0335x over previous
#include <cuda_runtime.h>
#include <cuda_fp16.h>
#include <cstdint>

// ---------------------------------------------------------------------------
// MHA.  R11: projection GEMMs moved to mma.sync m16n8k16 fp16 as well
// (same 10-bit mantissa as tf32; fp32 accumulation).  Attention = R10 fp16.
// ---------------------------------------------------------------------------

#define SEQ     2048
#define BATCH   2
#define NH      16
#define HD      64
#define HID     1024
#define MROWS   (BATCH * SEQ)   // 4096

__device__ float g_Q[MROWS * HID];
__device__ float g_K[MROWS * HID];
__device__ float g_V[MROWS * HID];
__device__ float g_O[MROWS * HID];

// ------------------------------ helpers ------------------------------------
__device__ __forceinline__ uint32_t packh2(float a, float b) {
    __half2 h = __floats2half2_rn(a, b);
    return *(uint32_t*)&h;
}

__device__ __forceinline__ void mma_f16(float* d, const uint32_t* a,
                                        uint32_t b0, uint32_t b1) {
    asm volatile(
        "mma.sync.aligned.m16n8k16.row.col.f32.f16.f16.f32 "
        "{%0,%1,%2,%3}, {%4,%5,%6,%7}, {%8,%9}, {%0,%1,%2,%3};"
        : "+f"(d[0]), "+f"(d[1]), "+f"(d[2]), "+f"(d[3])
        : "r"(a[0]), "r"(a[1]), "r"(a[2]), "r"(a[3]), "r"(b0), "r"(b1));
}

// ============================ fp16 GEMM ====================================
// C[M,N] = A[M,K] @ B[K,N] + bias[N].  128x128x32 tiles, 8 warps (2x4),
// warp tile 64x32, m16n8k16.  A: [m][k2] fp16 pairs (pad 20 u32);
// B: k-pair-interleaved [k2][n] (pad 136 u32).  Double-buffered.
#define GA 20
#define GB 136
#define GEMM_SMEM ((2 * (128 * GA + 16 * GB)) * 4)   // 37888 bytes

__global__ __launch_bounds__(256) void gemm_tc(
    const float* __restrict__ A, int lda,
    const float* __restrict__ B, int ldb,
    const float* __restrict__ bias,
    float* __restrict__ C, int ldc, int K)
{
    extern __shared__ uint32_t smg[];
    uint32_t* Asm = smg;                 // [2][128*GA]
    uint32_t* Bsm = smg + 2 * 128 * GA;  // [2][16*GB]

    const int tid  = threadIdx.x;
    const int wid  = tid >> 5, lane = tid & 31;
    const int g    = lane >> 2, t = lane & 3;
    const int wr   = wid & 1,  wc = wid >> 1;
    const int row0 = blockIdx.y * 128;
    const int col0 = blockIdx.x * 128;

    // staging maps
    const int ar = tid >> 1, ac = (tid & 1) * 8;    // A: row ar, u32 cols ac..ac+7
    const int pb = tid >> 4, nb = (tid & 15) * 8;   // B: k-pair pb, n cols nb..nb+7

    const float* Ag = A + (size_t)row0 * lda;
    const float* Bg = B + col0;

    float4 ra[4], rb[4];
    const int NT = K >> 5;

    // ---- prologue: load + stage chunk 0 ----
    #pragma unroll
    for (int i = 0; i < 4; i++)
        ra[i] = *(const float4*)(Ag + (size_t)ar * lda + ac * 2 + 4 * i);
    rb[0] = *(const float4*)(Bg + (size_t)(2 * pb)     * ldb + nb);
    rb[1] = *(const float4*)(Bg + (size_t)(2 * pb)     * ldb + nb + 4);
    rb[2] = *(const float4*)(Bg + (size_t)(2 * pb + 1) * ldb + nb);
    rb[3] = *(const float4*)(Bg + (size_t)(2 * pb + 1) * ldb + nb + 4);
    {
        uint32_t ta[8];
        #pragma unroll
        for (int i = 0; i < 4; i++) {
            ta[2 * i + 0] = packh2(ra[i].x, ra[i].y);
            ta[2 * i + 1] = packh2(ra[i].z, ra[i].w);
        }
        *(uint4*)&Asm[ar * GA + ac]     = *(uint4*)&ta[0];
        *(uint4*)&Asm[ar * GA + ac + 4] = *(uint4*)&ta[4];

        const float* r0 = (const float*)&rb[0];
        const float* r1 = (const float*)&rb[2];
        uint32_t tb[8];
        #pragma unroll
        for (int i = 0; i < 8; i++) tb[i] = packh2(r0[i], r1[i]);
        *(uint4*)&Bsm[pb * GB + nb]     = *(uint4*)&tb[0];
        *(uint4*)&Bsm[pb * GB + nb + 4] = *(uint4*)&tb[4];
    }
    __syncthreads();

    float acc[4][4][4] = {};

    for (int kt = 0; kt < NT; kt++) {
        if (kt + 1 < NT) {
            const int k0 = (kt + 1) * 32;
            #pragma unroll
            for (int i = 0; i < 4; i++)
                ra[i] = *(const float4*)(Ag + (size_t)ar * lda + k0 + ac * 2 + 4 * i);
            rb[0] = *(const float4*)(Bg + (size_t)(k0 + 2 * pb)     * ldb + nb);
            rb[1] = *(const float4*)(Bg + (size_t)(k0 + 2 * pb)     * ldb + nb + 4);
            rb[2] = *(const float4*)(Bg + (size_t)(k0 + 2 * pb + 1) * ldb + nb);
            rb[3] = *(const float4*)(Bg + (size_t)(k0 + 2 * pb + 1) * ldb + nb + 4);
        }

        const uint32_t* Ac = Asm + (kt & 1) * 128 * GA;
        const uint32_t* Bc = Bsm + (kt & 1) * 16 * GB;

        #pragma unroll
        for (int ks = 0; ks < 2; ks++) {
            uint32_t af[4][4];
            #pragma unroll
            for (int mt = 0; mt < 4; mt++) {
                const uint32_t* ap = Ac + (wr * 64 + mt * 16) * GA + ks * 8;
                af[mt][0] = ap[ g      * GA + t    ];
                af[mt][1] = ap[(g + 8) * GA + t    ];
                af[mt][2] = ap[ g      * GA + t + 4];
                af[mt][3] = ap[(g + 8) * GA + t + 4];
            }
            #pragma unroll
            for (int nt = 0; nt < 4; nt++) {
                const int ncol = wc * 32 + nt * 8 + g;
                uint32_t b0 = Bc[(ks * 8 + t    ) * GB + ncol];
                uint32_t b1 = Bc[(ks * 8 + t + 4) * GB + ncol];
                #pragma unroll
                for (int mt = 0; mt < 4; mt++)
                    mma_f16(acc[mt][nt], af[mt], b0, b1);
            }
        }

        if (kt + 1 < NT) {
            __syncthreads();
            uint32_t* Ad = Asm + ((kt + 1) & 1) * 128 * GA;
            uint32_t* Bd = Bsm + ((kt + 1) & 1) * 16 * GB;
            uint32_t ta[8];
            #pragma unroll
            for (int i = 0; i < 4; i++) {
                ta[2 * i + 0] = packh2(ra[i].x, ra[i].y);
                ta[2 * i + 1] = packh2(ra[i].z, ra[i].w);
            }
            *(uint4*)&Ad[ar * GA + ac]     = *(uint4*)&ta[0];
            *(uint4*)&Ad[ar * GA + ac + 4] = *(uint4*)&ta[4];

            const float* r0 = (const float*)&rb[0];
            const float* r1 = (const float*)&rb[2];
            uint32_t tb[8];
            #pragma unroll
            for (int i = 0; i < 8; i++) tb[i] = packh2(r0[i], r1[i]);
            *(uint4*)&Bd[pb * GB + nb]     = *(uint4*)&tb[0];
            *(uint4*)&Bd[pb * GB + nb + 4] = *(uint4*)&tb[4];
            __syncthreads();
        }
    }

    // ---- epilogue ----
    #pragma unroll
    for (int mt = 0; mt < 4; mt++) {
        const int row = row0 + wr * 64 + mt * 16 + g;
        #pragma unroll
        for (int nt = 0; nt < 4; nt++) {
            const int col = col0 + wc * 32 + nt * 8 + 2 * t;
            float2 bb = *(const float2*)&bias[col];
            float2 v0 = {acc[mt][nt][0] + bb.x, acc[mt][nt][1] + bb.y};
            float2 v1 = {acc[mt][nt][2] + bb.x, acc[mt][nt][3] + bb.y};
            *(float2*)&C[(size_t)row * ldc + col]       = v0;
            *(float2*)&C[(size_t)(row + 8) * ldc + col] = v1;
        }
    }
}

// ============================ attention (fp16 mma, R10) ====================
#define PADK 36
#define PADV 72
#define PADQ 36
#define ATTN_SMEM ((64*PADK + 32*PADV + 256*PADQ) * 4)   // 55296 bytes

__global__ __launch_bounds__(256, 1) void attn_tc(
    const float* __restrict__ Q,
    const float* __restrict__ Kin,
    const float* __restrict__ V,
    float* __restrict__ O)
{
    extern __shared__ uint32_t smu[];
    uint32_t* ksm = smu;                      // [j][d2]   64 x PADK
    uint32_t* vsm = smu + 64 * PADK;          // [j2][d]   32 x PADV
    uint32_t* qps = smu + 64 * PADK + 32 * PADV;   // Q stage / P slabs 256 x PADQ

    const int tid  = threadIdx.x;
    const int wid  = tid >> 5, lane = tid & 31;
    const int g    = lane >> 2, t = lane & 3;
    const int b    = blockIdx.z;
    const int h    = blockIdx.y;
    const int q0   = blockIdx.x * 256;
    const float C2 = 0.125f * 1.44269504088896340736f;   // scale*log2(e)

    const float* Qg = Q   + ((size_t)b * SEQ + q0) * HID + h * HD;
    const float* Kg = Kin + (size_t)b * SEQ * HID + h * HD;
    const float* Vg = V   + (size_t)b * SEQ * HID + h * HD;

    // ---- stage Q as fp16 pairs into qps ----
    for (int idx = tid; idx < 1024; idx += 256) {
        const int r = idx >> 2, sg = (idx & 3) * 8;
        const float* src = Qg + (size_t)r * HID + sg * 2;
        uint32_t tmp[8];
        #pragma unroll
        for (int i = 0; i < 4; i++) {
            float4 v = *(const float4*)(src + 4 * i);
            tmp[2 * i + 0] = packh2(v.x, v.y);
            tmp[2 * i + 1] = packh2(v.z, v.w);
        }
        *(uint4*)&qps[r * PADQ + sg]     = *(uint4*)&tmp[0];
        *(uint4*)&qps[r * PADQ + sg + 4] = *(uint4*)&tmp[4];
    }
    __syncthreads();

    uint32_t qf[2][4][4];
    #pragma unroll
    for (int mt = 0; mt < 2; mt++) {
        const int r0 = (wid * 32 + mt * 16 + g) * PADQ;
        const int r1 = r0 + 8 * PADQ;
        #pragma unroll
        for (int ks = 0; ks < 4; ks++) {
            qf[mt][ks][0] = qps[r0 + ks * 8 + t    ];
            qf[mt][ks][1] = qps[r1 + ks * 8 + t    ];
            qf[mt][ks][2] = qps[r0 + ks * 8 + t + 4];
            qf[mt][ks][3] = qps[r1 + ks * 8 + t + 4];
        }
    }
    __syncthreads();

    float oacc[2][8][4] = {};
    float m[2][2], l[2][2];
    #pragma unroll
    for (int mt = 0; mt < 2; mt++) {
        m[mt][0] = -1e30f; m[mt][1] = -1e30f;
        l[mt][0] = 0.0f;   l[mt][1] = 0.0f;
    }

    const int jk = tid >> 2, ck = (tid & 3) * 8;
    const int pv = tid >> 3, cv = (tid & 7) * 8;

    uint32_t* Pw = qps + wid * 32 * PADQ;

    for (int kv0 = 0; kv0 < SEQ; kv0 += 64) {
        __syncthreads();

        {
            const float* src = Kg + (size_t)(kv0 + jk) * HID + ck * 2;
            uint32_t tmp[8];
            #pragma unroll
            for (int i = 0; i < 4; i++) {
                float4 v = *(const float4*)(src + 4 * i);
                tmp[2 * i + 0] = packh2(v.x, v.y);
                tmp[2 * i + 1] = packh2(v.z, v.w);
            }
            *(uint4*)&ksm[jk * PADK + ck]     = *(uint4*)&tmp[0];
            *(uint4*)&ksm[jk * PADK + ck + 4] = *(uint4*)&tmp[4];
        }
        {
            const float* s0 = Vg + (size_t)(kv0 + 2 * pv)     * HID + cv;
            const float* s1 = Vg + (size_t)(kv0 + 2 * pv + 1) * HID + cv;
            float4 a0 = *(const float4*)(s0);
            float4 a1 = *(const float4*)(s0 + 4);
            float4 b0 = *(const float4*)(s1);
            float4 b1 = *(const float4*)(s1 + 4);
            uint32_t tmp[8];
            tmp[0] = packh2(a0.x, b0.x); tmp[1] = packh2(a0.y, b0.y);
            tmp[2] = packh2(a0.z, b0.z); tmp[3] = packh2(a0.w, b0.w);
            tmp[4] = packh2(a1.x, b1.x); tmp[5] = packh2(a1.y, b1.y);
            tmp[6] = packh2(a1.z, b1.z); tmp[7] = packh2(a1.w, b1.w);
            *(uint4*)&vsm[pv * PADV + cv]     = *(uint4*)&tmp[0];
            *(uint4*)&vsm[pv * PADV + cv + 4] = *(uint4*)&tmp[4];
        }
        __syncthreads();

        float s[2][8][4] = {};
        #pragma unroll
        for (int nt = 0; nt < 8; nt++) {
            const uint32_t* kp = ksm + (nt * 8 + g) * PADK;
            #pragma unroll
            for (int ks = 0; ks < 4; ks++) {
                uint32_t b0 = kp[ks * 8 + t];
                uint32_t b1 = kp[ks * 8 + t + 4];
                mma_f16(s[0][nt], qf[0][ks], b0, b1);
                mma_f16(s[1][nt], qf[1][ks], b0, b1);
            }
        }

        #pragma unroll
        for (int mt = 0; mt < 2; mt++) {
            float rm0 = -1e30f, rm1 = -1e30f;
            #pragma unroll
            for (int nt = 0; nt < 8; nt++) {
                rm0 = fmaxf(rm0, fmaxf(s[mt][nt][0], s[mt][nt][1]));
                rm1 = fmaxf(rm1, fmaxf(s[mt][nt][2], s[mt][nt][3]));
            }
            rm0 = fmaxf(rm0, __shfl_xor_sync(0xffffffffu, rm0, 1));
            rm0 = fmaxf(rm0, __shfl_xor_sync(0xffffffffu, rm0, 2));
            rm1 = fmaxf(rm1, __shfl_xor_sync(0xffffffffu, rm1, 1));
            rm1 = fmaxf(rm1, __shfl_xor_sync(0xffffffffu, rm1, 2));

            const float nm0 = fmaxf(m[mt][0], rm0), nm1 = fmaxf(m[mt][1], rm1);
            const float a0 = exp2f((m[mt][0] - nm0) * C2);
            const float a1 = exp2f((m[mt][1] - nm1) * C2);
            const float mc0 = nm0 * C2, mc1 = nm1 * C2;
            float sum0 = 0.0f, sum1 = 0.0f;
            #pragma unroll
            for (int nt = 0; nt < 8; nt++) {
                s[mt][nt][0] = exp2f(fmaf(s[mt][nt][0], C2, -mc0)); sum0 += s[mt][nt][0];
                s[mt][nt][1] = exp2f(fmaf(s[mt][nt][1], C2, -mc0)); sum0 += s[mt][nt][1];
                s[mt][nt][2] = exp2f(fmaf(s[mt][nt][2], C2, -mc1)); sum1 += s[mt][nt][2];
                s[mt][nt][3] = exp2f(fmaf(s[mt][nt][3], C2, -mc1)); sum1 += s[mt][nt][3];
            }
            sum0 += __shfl_xor_sync(0xffffffffu, sum0, 1);
            sum0 += __shfl_xor_sync(0xffffffffu, sum0, 2);
            sum1 += __shfl_xor_sync(0xffffffffu, sum1, 1);
            sum1 += __shfl_xor_sync(0xffffffffu, sum1, 2);

            l[mt][0] = l[mt][0] * a0 + sum0;
            l[mt][1] = l[mt][1] * a1 + sum1;
            m[mt][0] = nm0; m[mt][1] = nm1;
            #pragma unroll
            for (int nt = 0; nt < 8; nt++) {
                oacc[mt][nt][0] *= a0; oacc[mt][nt][1] *= a0;
                oacc[mt][nt][2] *= a1; oacc[mt][nt][3] *= a1;
            }

            #pragma unroll
            for (int nt = 0; nt < 8; nt++) {
                Pw[(mt * 16 + g    ) * PADQ + nt * 4 + t] = packh2(s[mt][nt][0], s[mt][nt][1]);
                Pw[(mt * 16 + g + 8) * PADQ + nt * 4 + t] = packh2(s[mt][nt][2], s[mt][nt][3]);
            }
        }
        __syncwarp();

        #pragma unroll
        for (int ks = 0; ks < 4; ks++) {
            uint32_t af[2][4];
            #pragma unroll
            for (int mt = 0; mt < 2; mt++) {
                const uint32_t* pp = Pw + (mt * 16 + g) * PADQ;
                af[mt][0] = pp[ks * 8 + t];
                af[mt][1] = pp[8 * PADQ + ks * 8 + t];
                af[mt][2] = pp[ks * 8 + t + 4];
                af[mt][3] = pp[8 * PADQ + ks * 8 + t + 4];
            }
            #pragma unroll
            for (int nt = 0; nt < 8; nt++) {
                uint32_t b0 = vsm[(ks * 8 + t    ) * PADV + nt * 8 + g];
                uint32_t b1 = vsm[(ks * 8 + t + 4) * PADV + nt * 8 + g];
                mma_f16(oacc[0][nt], af[0], b0, b1);
                mma_f16(oacc[1][nt], af[1], b0, b1);
            }
        }
        __syncwarp();
    }

    #pragma unroll
    for (int mt = 0; mt < 2; mt++) {
        const float inv0 = 1.0f / l[mt][0], inv1 = 1.0f / l[mt][1];
        float* Og = O + ((size_t)b * SEQ + q0 + wid * 32 + mt * 16) * HID + h * HD;
        #pragma unroll
        for (int nt = 0; nt < 8; nt++) {
            const int col = nt * 8 + 2 * t;
            float2 v0 = {oacc[mt][nt][0] * inv0, oacc[mt][nt][1] * inv0};
            float2 v1 = {oacc[mt][nt][2] * inv1, oacc[mt][nt][3] * inv1};
            *(float2*)&Og[(size_t) g      * HID + col] = v0;
            *(float2*)&Og[(size_t)(g + 8) * HID + col] = v1;
        }
    }
}

// ===========================================================================
extern "C" void kernel_launch(void* const* d_in, const int* in_sizes, int n_in,
                              void* d_out, int out_size)
{
    const float* q   = (const float*)d_in[0];
    const float* Wq  = (const float*)d_in[1];
    const float* bq  = (const float*)d_in[2];
    const float* Wkv = (const float*)d_in[3];
    const float* bkv = (const float*)d_in[4];
    const float* Wo  = (const float*)d_in[5];
    const float* bo  = (const float*)d_in[6];
    float* out = (float*)d_out;

    void *pQ, *pK, *pV, *pO;
    cudaGetSymbolAddress(&pQ, g_Q);
    cudaGetSymbolAddress(&pK, g_K);
    cudaGetSymbolAddress(&pV, g_V);
    cudaGetSymbolAddress(&pO, g_O);
    float* gQ = (float*)pQ;
    float* gK = (float*)pK;
    float* gV = (float*)pV;
    float* gO = (float*)pO;

    cudaFuncSetAttribute(gemm_tc, cudaFuncAttributeMaxDynamicSharedMemorySize,
                         GEMM_SMEM);
    cudaFuncSetAttribute(attn_tc, cudaFuncAttributeMaxDynamicSharedMemorySize,
                         ATTN_SMEM);

    dim3 ggrid(HID / 128, MROWS / 128);

    gemm_tc<<<ggrid, 256, GEMM_SMEM>>>(q, HID, Wq, HID, bq, gQ, HID, HID);
    gemm_tc<<<ggrid, 256, GEMM_SMEM>>>(q, HID, Wkv, 2 * HID, bkv, gK, HID, HID);
    gemm_tc<<<ggrid, 256, GEMM_SMEM>>>(q, HID, Wkv + HID, 2 * HID, bkv + HID,
                                       gV, HID, HID);

    dim3 agrid(SEQ / 256, NH, BATCH);     // (8, 16, 2) = 256 CTAs
    attn_tc<<<agrid, 256, ATTN_SMEM>>>(gQ, gK, gV, gO);

    gemm_tc<<<ggrid, 256, GEMM_SMEM>>>(gO, HID, Wo, HID, bo, out, HID, HID);
}

// round 12
// speedup vs baseline: 1.9060x; 1.3374x over previous
#include <cuda_runtime.h>
#include <cuda_fp16.h>
#include <cstdint>

// ---------------------------------------------------------------------------
// MHA.  R12: end-to-end fp16 dataflow.  Pre-pass converts q + weights to
// fp16 once; fused QKV GEMM (N=3072) and O-proj GEMM are fp16-in (BK=64,
// single barrier/chunk, raw-copy staging); attention reads/writes fp16.
// fp32 accumulation everywhere; rounding points identical to R11.
// ---------------------------------------------------------------------------

#define SEQ     2048
#define BATCH   2
#define NH      16
#define HD      64
#define HID     1024
#define HID3    3072
#define MROWS   (BATCH * SEQ)   // 4096

__device__ __half g_Ah[MROWS * HID];          // q in fp16
__device__ __half g_Wf[HID * HID3];           // [Wq | Wkv] fp16
__device__ __half g_Woh[HID * HID];           // Wo fp16
__device__ float  g_bf[HID3];                 // [bq | bkv]
__device__ __half g_QKVh[(size_t)MROWS * HID3];
__device__ __half g_Oh[MROWS * HID];

// ------------------------------ helpers ------------------------------------
__device__ __forceinline__ uint32_t packh2(float a, float b) {
    __half2 h = __floats2half2_rn(a, b);
    return *(uint32_t*)&h;
}

__device__ __forceinline__ uint32_t prmt(uint32_t a, uint32_t b, uint32_t s) {
    uint32_t d;
    asm("prmt.b32 %0, %1, %2, %3;" : "=r"(d) : "r"(a), "r"(b), "r"(s));
    return d;
}

__device__ __forceinline__ void mma_f16(float* d, const uint32_t* a,
                                        uint32_t b0, uint32_t b1) {
    asm volatile(
        "mma.sync.aligned.m16n8k16.row.col.f32.f16.f16.f32 "
        "{%0,%1,%2,%3}, {%4,%5,%6,%7}, {%8,%9}, {%0,%1,%2,%3};"
        : "+f"(d[0]), "+f"(d[1]), "+f"(d[2]), "+f"(d[3])
        : "r"(a[0]), "r"(a[1]), "r"(a[2]), "r"(a[3]), "r"(b0), "r"(b1));
}

// ============================ pre-pass ======================================
__global__ void cvt16(const float* __restrict__ src, __half* __restrict__ dst) {
    size_t i = ((size_t)blockIdx.x * 256 + threadIdx.x) * 8;
    float4 a = *(const float4*)(src + i);
    float4 b = *(const float4*)(src + i + 4);
    uint4 v = {packh2(a.x, a.y), packh2(a.z, a.w),
               packh2(b.x, b.y), packh2(b.z, b.w)};
    *(uint4*)(dst + i) = v;
}

__global__ void fuseW(const float* __restrict__ Wq, const float* __restrict__ Wkv,
                      const float* __restrict__ bq, const float* __restrict__ bkv,
                      __half* __restrict__ Wf, float* __restrict__ bf) {
    int gid = blockIdx.x * 256 + threadIdx.x;
    size_t e = (size_t)gid * 8;
    int r = (int)(e / HID3), c = (int)(e % HID3);
    const float* src = (c < HID) ? Wq + (size_t)r * HID + c
                                 : Wkv + (size_t)r * (2 * HID) + (c - HID);
    float4 a = *(const float4*)src;
    float4 b = *(const float4*)(src + 4);
    uint4 v = {packh2(a.x, a.y), packh2(a.z, a.w),
               packh2(b.x, b.y), packh2(b.z, b.w)};
    *(uint4*)(Wf + e) = v;
    if (gid < HID3 / 8) {
        int cb = gid * 8;
        const float* sb = (cb < HID) ? bq + cb : bkv + (cb - HID);
        *(float4*)(bf + cb)     = *(const float4*)sb;
        *(float4*)(bf + cb + 4) = *(const float4*)(sb + 4);
    }
}

// ============================ fp16 GEMM =====================================
// C[M,N] = A[M,K] @ B[K,N] + bias[N].  A,B fp16; C fp16 or fp32.
// 128x128x64 tiles, 8 warps (2x4), warp tile 64x32, m16n8k16.
// A smem: [m][k2] pad GA; B smem: k-pair-interleaved [k2][n] pad GB.
// Double-buffered, single barrier per chunk.
#define GA 36
#define GB 136
#define GEMM_SMEM ((2 * (128 * GA + 32 * GB)) * 4)   // 71680 bytes

__global__ __launch_bounds__(256, 2) void gemm_f16(
    const __half* __restrict__ A, int lda,
    const __half* __restrict__ B, int ldb,
    const float* __restrict__ bias,
    void* __restrict__ Cout, int ldc, int K, int fp16out)
{
    extern __shared__ uint32_t smg[];
    uint32_t* Asm = smg;                 // [2][128*GA]
    uint32_t* Bsm = smg + 2 * 128 * GA;  // [2][32*GB]

    const int tid  = threadIdx.x;
    const int wid  = tid >> 5, lane = tid & 31;
    const int g    = lane >> 2, t = lane & 3;
    const int wr   = wid & 1,  wc = wid >> 1;
    const int row0 = blockIdx.y * 128;
    const int col0 = blockIdx.x * 128;

    // staging maps
    const int ar = tid >> 1, akb = (tid & 1) * 16;   // A: row ar, u32 cols akb..+15
    const int kp = tid >> 3, nb  = (tid & 7) * 16;   // B: k-pair kp, n cols nb..+15

    const __half* Ag = A + (size_t)row0 * lda;
    const __half* Bg = B + col0;

    uint4 ra[4], rbx0, rbx1, rby0, rby1;
    const int NT = K >> 6;

    // ---- prologue: load + stage chunk 0 ----
    #pragma unroll
    for (int i = 0; i < 4; i++)
        ra[i] = *(const uint4*)(Ag + (size_t)ar * lda + akb * 2 + 8 * i);
    {
        const __half* s0 = Bg + (size_t)(2 * kp) * ldb + nb;
        const __half* s1 = s0 + ldb;
        rbx0 = *(const uint4*)s0; rbx1 = *(const uint4*)(s0 + 8);
        rby0 = *(const uint4*)s1; rby1 = *(const uint4*)(s1 + 8);
    }
    {
        *(uint4*)&Asm[ar * GA + akb]      = ra[0];
        *(uint4*)&Asm[ar * GA + akb + 4]  = ra[1];
        *(uint4*)&Asm[ar * GA + akb + 8]  = ra[2];
        *(uint4*)&Asm[ar * GA + akb + 12] = ra[3];
        const uint32_t* xu = (const uint32_t*)&rbx0;   // rbx0,rbx1 contiguous? no-
        uint32_t xa[8] = {rbx0.x, rbx0.y, rbx0.z, rbx0.w, rbx1.x, rbx1.y, rbx1.z, rbx1.w};
        uint32_t ya[8] = {rby0.x, rby0.y, rby0.z, rby0.w, rby1.x, rby1.y, rby1.z, rby1.w};
        (void)xu;
        uint32_t z[16];
        #pragma unroll
        for (int i = 0; i < 8; i++) {
            z[2 * i + 0] = prmt(xa[i], ya[i], 0x5410);
            z[2 * i + 1] = prmt(xa[i], ya[i], 0x7632);
        }
        *(uint4*)&Bsm[kp * GB + nb]      = *(uint4*)&z[0];
        *(uint4*)&Bsm[kp * GB + nb + 4]  = *(uint4*)&z[4];
        *(uint4*)&Bsm[kp * GB + nb + 8]  = *(uint4*)&z[8];
        *(uint4*)&Bsm[kp * GB + nb + 12] = *(uint4*)&z[12];
    }
    __syncthreads();

    float acc[4][4][4] = {};

    for (int kt = 0; kt < NT; kt++) {
        if (kt + 1 < NT) {
            const int kc = (kt + 1) * 64;
            #pragma unroll
            for (int i = 0; i < 4; i++)
                ra[i] = *(const uint4*)(Ag + (size_t)ar * lda + kc + akb * 2 + 8 * i);
            const __half* s0 = Bg + (size_t)(kc + 2 * kp) * ldb + nb;
            const __half* s1 = s0 + ldb;
            rbx0 = *(const uint4*)s0; rbx1 = *(const uint4*)(s0 + 8);
            rby0 = *(const uint4*)s1; rby1 = *(const uint4*)(s1 + 8);
        }

        const uint32_t* Ac = Asm + (kt & 1) * 128 * GA;
        const uint32_t* Bc = Bsm + (kt & 1) * 32 * GB;

        #pragma unroll
        for (int ks = 0; ks < 4; ks++) {
            uint32_t af[4][4];
            #pragma unroll
            for (int mt = 0; mt < 4; mt++) {
                const uint32_t* ap = Ac + (wr * 64 + mt * 16) * GA + ks * 8;
                af[mt][0] = ap[ g      * GA + t    ];
                af[mt][1] = ap[(g + 8) * GA + t    ];
                af[mt][2] = ap[ g      * GA + t + 4];
                af[mt][3] = ap[(g + 8) * GA + t + 4];
            }
            #pragma unroll
            for (int nt = 0; nt < 4; nt++) {
                const int ncol = wc * 32 + nt * 8 + g;
                uint32_t b0 = Bc[(ks * 8 + t    ) * GB + ncol];
                uint32_t b1 = Bc[(ks * 8 + t + 4) * GB + ncol];
                #pragma unroll
                for (int mt = 0; mt < 4; mt++)
                    mma_f16(acc[mt][nt], af[mt], b0, b1);
            }
        }

        if (kt + 1 < NT) {
            // other warps finished computing this buffer at barrier(kt-1)
            uint32_t* Ad = Asm + ((kt + 1) & 1) * 128 * GA;
            uint32_t* Bd = Bsm + ((kt + 1) & 1) * 32 * GB;
            *(uint4*)&Ad[ar * GA + akb]      = ra[0];
            *(uint4*)&Ad[ar * GA + akb + 4]  = ra[1];
            *(uint4*)&Ad[ar * GA + akb + 8]  = ra[2];
            *(uint4*)&Ad[ar * GA + akb + 12] = ra[3];
            uint32_t xa[8] = {rbx0.x, rbx0.y, rbx0.z, rbx0.w, rbx1.x, rbx1.y, rbx1.z, rbx1.w};
            uint32_t ya[8] = {rby0.x, rby0.y, rby0.z, rby0.w, rby1.x, rby1.y, rby1.z, rby1.w};
            uint32_t z[16];
            #pragma unroll
            for (int i = 0; i < 8; i++) {
                z[2 * i + 0] = prmt(xa[i], ya[i], 0x5410);
                z[2 * i + 1] = prmt(xa[i], ya[i], 0x7632);
            }
            *(uint4*)&Bd[kp * GB + nb]      = *(uint4*)&z[0];
            *(uint4*)&Bd[kp * GB + nb + 4]  = *(uint4*)&z[4];
            *(uint4*)&Bd[kp * GB + nb + 8]  = *(uint4*)&z[8];
            *(uint4*)&Bd[kp * GB + nb + 12] = *(uint4*)&z[12];
            __syncthreads();
        }
    }

    // ---- epilogue ----
    if (fp16out) {
        __half* Ch = (__half*)Cout;
        #pragma unroll
        for (int mt = 0; mt < 4; mt++) {
            const int row = row0 + wr * 64 + mt * 16 + g;
            #pragma unroll
            for (int nt = 0; nt < 4; nt++) {
                const int col = col0 + wc * 32 + nt * 8 + 2 * t;
                float2 bb = *(const float2*)&bias[col];
                *(uint32_t*)&Ch[(size_t)row * ldc + col] =
                    packh2(acc[mt][nt][0] + bb.x, acc[mt][nt][1] + bb.y);
                *(uint32_t*)&Ch[(size_t)(row + 8) * ldc + col] =
                    packh2(acc[mt][nt][2] + bb.x, acc[mt][nt][3] + bb.y);
            }
        }
    } else {
        float* Cf = (float*)Cout;
        #pragma unroll
        for (int mt = 0; mt < 4; mt++) {
            const int row = row0 + wr * 64 + mt * 16 + g;
            #pragma unroll
            for (int nt = 0; nt < 4; nt++) {
                const int col = col0 + wc * 32 + nt * 8 + 2 * t;
                float2 bb = *(const float2*)&bias[col];
                float2 v0 = {acc[mt][nt][0] + bb.x, acc[mt][nt][1] + bb.y};
                float2 v1 = {acc[mt][nt][2] + bb.x, acc[mt][nt][3] + bb.y};
                *(float2*)&Cf[(size_t)row * ldc + col]       = v0;
                *(float2*)&Cf[(size_t)(row + 8) * ldc + col] = v1;
            }
        }
    }
}

// ============================ attention (fp16 in/out) ======================
#define PADK 36
#define PADV 72
#define PADQ 36
#define ATTN_SMEM ((64*PADK + 32*PADV + 256*PADQ) * 4)   // 55296 bytes

__global__ __launch_bounds__(256, 1) void attn_tc(
    const __half* __restrict__ QKV,
    __half* __restrict__ O)
{
    extern __shared__ uint32_t smu[];
    uint32_t* ksm = smu;                      // [j][d2]   64 x PADK
    uint32_t* vsm = smu + 64 * PADK;          // [j2][d]   32 x PADV
    uint32_t* qps = smu + 64 * PADK + 32 * PADV;   // Q stage / P slabs 256 x PADQ

    const int tid  = threadIdx.x;
    const int wid  = tid >> 5, lane = tid & 31;
    const int g    = lane >> 2, t = lane & 3;
    const int b    = blockIdx.z;
    const int h    = blockIdx.y;
    const int q0   = blockIdx.x * 256;
    const float C2 = 0.125f * 1.44269504088896340736f;   // scale*log2(e)

    const __half* Qh = QKV + ((size_t)b * SEQ + q0) * HID3 + h * HD;
    const __half* Kh = QKV + (size_t)b * SEQ * HID3 + HID + h * HD;
    const __half* Vh = QKV + (size_t)b * SEQ * HID3 + 2 * HID + h * HD;

    // ---- stage Q: raw copy (row r = tid, 32 u32) ----
    {
        const uint4* src = (const uint4*)(Qh + (size_t)tid * HID3);
        uint32_t* dst = qps + tid * PADQ;
        #pragma unroll
        for (int i = 0; i < 8; i++) *(uint4*)(dst + 4 * i) = src[i];
    }
    __syncthreads();

    uint32_t qf[2][4][4];
    #pragma unroll
    for (int mt = 0; mt < 2; mt++) {
        const int r0 = (wid * 32 + mt * 16 + g) * PADQ;
        const int r1 = r0 + 8 * PADQ;
        #pragma unroll
        for (int ks = 0; ks < 4; ks++) {
            qf[mt][ks][0] = qps[r0 + ks * 8 + t    ];
            qf[mt][ks][1] = qps[r1 + ks * 8 + t    ];
            qf[mt][ks][2] = qps[r0 + ks * 8 + t + 4];
            qf[mt][ks][3] = qps[r1 + ks * 8 + t + 4];
        }
    }
    __syncthreads();

    float oacc[2][8][4] = {};
    float m[2][2], l[2][2];
    #pragma unroll
    for (int mt = 0; mt < 2; mt++) {
        m[mt][0] = -1e30f; m[mt][1] = -1e30f;
        l[mt][0] = 0.0f;   l[mt][1] = 0.0f;
    }

    const int jk = tid >> 2, ckb = (tid & 3) * 8;   // K: row jk, u32 cols ckb..+7
    const int pv = tid >> 3, db  = (tid & 7) * 8;   // V: pair pv, d cols db..+7

    uint32_t* Pw = qps + wid * 32 * PADQ;

    for (int kv0 = 0; kv0 < SEQ; kv0 += 64) {
        __syncthreads();

        // K: raw copy
        {
            const uint4* src = (const uint4*)(Kh + (size_t)(kv0 + jk) * HID3 + ckb * 2);
            *(uint4*)&ksm[jk * PADK + ckb]     = src[0];
            *(uint4*)&ksm[jk * PADK + ckb + 4] = src[1];
        }
        // V: pair-interleave rows 2pv,2pv+1 via PRMT
        {
            uint4 x = *(const uint4*)(Vh + (size_t)(kv0 + 2 * pv) * HID3 + db);
            uint4 y = *(const uint4*)(Vh + (size_t)(kv0 + 2 * pv + 1) * HID3 + db);
            uint32_t z[8];
            z[0] = prmt(x.x, y.x, 0x5410); z[1] = prmt(x.x, y.x, 0x7632);
            z[2] = prmt(x.y, y.y, 0x5410); z[3] = prmt(x.y, y.y, 0x7632);
            z[4] = prmt(x.z, y.z, 0x5410); z[5] = prmt(x.z, y.z, 0x7632);
            z[6] = prmt(x.w, y.w, 0x5410); z[7] = prmt(x.w, y.w, 0x7632);
            *(uint4*)&vsm[pv * PADV + db]     = *(uint4*)&z[0];
            *(uint4*)&vsm[pv * PADV + db + 4] = *(uint4*)&z[4];
        }
        __syncthreads();

        // ---- S = Q K^T ----
        float s[2][8][4] = {};
        #pragma unroll
        for (int nt = 0; nt < 8; nt++) {
            const uint32_t* kpp = ksm + (nt * 8 + g) * PADK;
            #pragma unroll
            for (int ks = 0; ks < 4; ks++) {
                uint32_t b0 = kpp[ks * 8 + t];
                uint32_t b1 = kpp[ks * 8 + t + 4];
                mma_f16(s[0][nt], qf[0][ks], b0, b1);
                mma_f16(s[1][nt], qf[1][ks], b0, b1);
            }
        }

        // ---- online softmax ----
        #pragma unroll
        for (int mt = 0; mt < 2; mt++) {
            float rm0 = -1e30f, rm1 = -1e30f;
            #pragma unroll
            for (int nt = 0; nt < 8; nt++) {
                rm0 = fmaxf(rm0, fmaxf(s[mt][nt][0], s[mt][nt][1]));
                rm1 = fmaxf(rm1, fmaxf(s[mt][nt][2], s[mt][nt][3]));
            }
            rm0 = fmaxf(rm0, __shfl_xor_sync(0xffffffffu, rm0, 1));
            rm0 = fmaxf(rm0, __shfl_xor_sync(0xffffffffu, rm0, 2));
            rm1 = fmaxf(rm1, __shfl_xor_sync(0xffffffffu, rm1, 1));
            rm1 = fmaxf(rm1, __shfl_xor_sync(0xffffffffu, rm1, 2));

            const float nm0 = fmaxf(m[mt][0], rm0), nm1 = fmaxf(m[mt][1], rm1);
            const float a0 = exp2f((m[mt][0] - nm0) * C2);
            const float a1 = exp2f((m[mt][1] - nm1) * C2);
            const float mc0 = nm0 * C2, mc1 = nm1 * C2;
            float sum0 = 0.0f, sum1 = 0.0f;
            #pragma unroll
            for (int nt = 0; nt < 8; nt++) {
                s[mt][nt][0] = exp2f(fmaf(s[mt][nt][0], C2, -mc0)); sum0 += s[mt][nt][0];
                s[mt][nt][1] = exp2f(fmaf(s[mt][nt][1], C2, -mc0)); sum0 += s[mt][nt][1];
                s[mt][nt][2] = exp2f(fmaf(s[mt][nt][2], C2, -mc1)); sum1 += s[mt][nt][2];
                s[mt][nt][3] = exp2f(fmaf(s[mt][nt][3], C2, -mc1)); sum1 += s[mt][nt][3];
            }
            sum0 += __shfl_xor_sync(0xffffffffu, sum0, 1);
            sum0 += __shfl_xor_sync(0xffffffffu, sum0, 2);
            sum1 += __shfl_xor_sync(0xffffffffu, sum1, 1);
            sum1 += __shfl_xor_sync(0xffffffffu, sum1, 2);

            l[mt][0] = l[mt][0] * a0 + sum0;
            l[mt][1] = l[mt][1] * a1 + sum1;
            m[mt][0] = nm0; m[mt][1] = nm1;
            #pragma unroll
            for (int nt = 0; nt < 8; nt++) {
                oacc[mt][nt][0] *= a0; oacc[mt][nt][1] *= a0;
                oacc[mt][nt][2] *= a1; oacc[mt][nt][3] *= a1;
            }

            #pragma unroll
            for (int nt = 0; nt < 8; nt++) {
                Pw[(mt * 16 + g    ) * PADQ + nt * 4 + t] = packh2(s[mt][nt][0], s[mt][nt][1]);
                Pw[(mt * 16 + g + 8) * PADQ + nt * 4 + t] = packh2(s[mt][nt][2], s[mt][nt][3]);
            }
        }
        __syncwarp();

        // ---- O += P V ----
        #pragma unroll
        for (int ks = 0; ks < 4; ks++) {
            uint32_t af[2][4];
            #pragma unroll
            for (int mt = 0; mt < 2; mt++) {
                const uint32_t* pp = Pw + (mt * 16 + g) * PADQ;
                af[mt][0] = pp[ks * 8 + t];
                af[mt][1] = pp[8 * PADQ + ks * 8 + t];
                af[mt][2] = pp[ks * 8 + t + 4];
                af[mt][3] = pp[8 * PADQ + ks * 8 + t + 4];
            }
            #pragma unroll
            for (int nt = 0; nt < 8; nt++) {
                uint32_t b0 = vsm[(ks * 8 + t    ) * PADV + nt * 8 + g];
                uint32_t b1 = vsm[(ks * 8 + t + 4) * PADV + nt * 8 + g];
                mma_f16(oacc[0][nt], af[0], b0, b1);
                mma_f16(oacc[1][nt], af[1], b0, b1);
            }
        }
        __syncwarp();
    }

    // ---- epilogue (fp16 out) ----
    #pragma unroll
    for (int mt = 0; mt < 2; mt++) {
        const float inv0 = 1.0f / l[mt][0], inv1 = 1.0f / l[mt][1];
        __half* Og = O + ((size_t)b * SEQ + q0 + wid * 32 + mt * 16) * HID + h * HD;
        #pragma unroll
        for (int nt = 0; nt < 8; nt++) {
            const int col = nt * 8 + 2 * t;
            *(uint32_t*)&Og[(size_t) g      * HID + col] =
                packh2(oacc[mt][nt][0] * inv0, oacc[mt][nt][1] * inv0);
            *(uint32_t*)&Og[(size_t)(g + 8) * HID + col] =
                packh2(oacc[mt][nt][2] * inv1, oacc[mt][nt][3] * inv1);
        }
    }
}

// ===========================================================================
extern "C" void kernel_launch(void* const* d_in, const int* in_sizes, int n_in,
                              void* d_out, int out_size)
{
    const float* q   = (const float*)d_in[0];
    const float* Wq  = (const float*)d_in[1];
    const float* bq  = (const float*)d_in[2];
    const float* Wkv = (const float*)d_in[3];
    const float* bkv = (const float*)d_in[4];
    const float* Wo  = (const float*)d_in[5];
    const float* bo  = (const float*)d_in[6];
    float* out = (float*)d_out;

    void *pAh, *pWf, *pWoh, *pbf, *pQKV, *pOh;
    cudaGetSymbolAddress(&pAh, g_Ah);
    cudaGetSymbolAddress(&pWf, g_Wf);
    cudaGetSymbolAddress(&pWoh, g_Woh);
    cudaGetSymbolAddress(&pbf, g_bf);
    cudaGetSymbolAddress(&pQKV, g_QKVh);
    cudaGetSymbolAddress(&pOh, g_Oh);
    __half* Ah   = (__half*)pAh;
    __half* Wf   = (__half*)pWf;
    __half* Woh  = (__half*)pWoh;
    float*  bf   = (float*)pbf;
    __half* QKVh = (__half*)pQKV;
    __half* Oh   = (__half*)pOh;

    cudaFuncSetAttribute(gemm_f16, cudaFuncAttributeMaxDynamicSharedMemorySize,
                         GEMM_SMEM);
    cudaFuncSetAttribute(attn_tc, cudaFuncAttributeMaxDynamicSharedMemorySize,
                         ATTN_SMEM);

    // pre-pass: fp16 conversions (once per launch; deterministic)
    cvt16<<<MROWS * HID / (256 * 8), 256>>>(q, Ah);                 // 2048 blocks
    fuseW<<<HID * HID3 / (256 * 8), 256>>>(Wq, Wkv, bq, bkv, Wf, bf); // 1536
    cvt16<<<HID * HID / (256 * 8), 256>>>(Wo, Woh);                 // 512

    // fused QKV projection: [4096, 3072] fp16
    gemm_f16<<<dim3(HID3 / 128, MROWS / 128), 256, GEMM_SMEM>>>(
        Ah, HID, Wf, HID3, bf, QKVh, HID3, HID, 1);

    // attention
    dim3 agrid(SEQ / 256, NH, BATCH);     // (8, 16, 2)
    attn_tc<<<agrid, 256, ATTN_SMEM>>>(QKVh, Oh);

    // output projection: fp32 out
    gemm_f16<<<dim3(HID / 128, MROWS / 128), 256, GEMM_SMEM>>>(
        Oh, HID, Woh, HID, bo, out, HID, HID, 0);
}